// round 1
// baseline (speedup 1.0000x reference)
#include <cuda_runtime.h>

#define EPS_BN 1e-5f
#define SCALE_ATTN 0.125f
#define CDIM 512
#define MROWS 8192   // B*N = 8*1024

// ---------------- scratch (static device memory; no allocation) ----------------
__device__ float g_wq[CDIM*CDIM], g_wk[CDIM*CDIM], g_wv[CDIM*CDIM], g_wp[CDIM*CDIM];
__device__ float g_bq[CDIM], g_bk[CDIM], g_bv[CDIM], g_bp[CDIM];
__device__ float g_q[MROWS*CDIM], g_k[MROWS*CDIM], g_v[MROWS*CDIM];
__device__ float g_att[MROWS*CDIM];
__device__ float g_m[64*64*64];          // [b*8+h][64][64], SCALE applied
__device__ float g_mpart[4*64*64*64];    // 4 partial sums

// ---------------- fold BN into weights/bias ----------------
__global__ void fold_kernel(const float* __restrict__ w, const float* __restrict__ b,
                            const float* __restrict__ g, const float* __restrict__ beta,
                            const float* __restrict__ mu, const float* __restrict__ var,
                            int s)
{
    float* wOut = (s == 0) ? g_wq : (s == 1) ? g_wk : (s == 2) ? g_wv : g_wp;
    float* bOut = (s == 0) ? g_bq : (s == 1) ? g_bk : (s == 2) ? g_bv : g_bp;
    int i = blockIdx.x * blockDim.x + threadIdx.x;          // over 512*512
    int d = i >> 9;
    float sc = g[d] * rsqrtf(var[d] + EPS_BN);
    wOut[i] = w[i] * sc;
    if ((i & 511) == 0) bOut[d] = (b[d] - mu[d]) * sc + beta[d];
}

// ---------------- GEMM: C[m,n] = relu(sum_k A[m,k]*W[n,k] + bias[n]) ----------------
// A: [M,K] row-major, W: [N,K] row-major. 128x128x16 tiles, 256 threads, 8x8/thread.
// asel: 0 -> use Aext param, 1 -> g_att
// wsel: 0..3 -> g_wq/g_wk/g_wv/g_wp (+matching bias)
// osel: 0..2 -> g_q/g_k/g_v, 3 -> Cext param
__global__ __launch_bounds__(256, 2)
void gemm_bias_relu(const float* __restrict__ Aext, float* __restrict__ Cext,
                    int asel, int wsel, int osel, int M, int N, int K)
{
    const float* A = (asel == 0) ? Aext : g_att;
    const float* W = (wsel == 0) ? g_wq : (wsel == 1) ? g_wk : (wsel == 2) ? g_wv : g_wp;
    const float* bias = (wsel == 0) ? g_bq : (wsel == 1) ? g_bk : (wsel == 2) ? g_bv : g_bp;
    float* Cout = (osel == 0) ? g_q : (osel == 1) ? g_k : (osel == 2) ? g_v : Cext;

    __shared__ float As[16][132];
    __shared__ float Ws[16][132];

    int tid = threadIdx.x;
    int tx = tid & 15;       // n-group
    int ty = tid >> 4;       // m-group
    int bn = blockIdx.x * 128;
    int bm = blockIdx.y * 128;

    const float* Aptr = A + (size_t)bm * K;
    const float* Wptr = W + (size_t)bn * K;

    float acc[8][8];
#pragma unroll
    for (int i = 0; i < 8; ++i)
#pragma unroll
        for (int j = 0; j < 8; ++j) acc[i][j] = 0.f;

    float4 ra[2], rw[2];
    // prologue loads (kt = 0)
#pragma unroll
    for (int u = 0; u < 2; ++u) {
        int v = tid + u * 256;
        int row = v >> 2, kq = v & 3;
        ra[u] = *(const float4*)(Aptr + (size_t)row * K + kq * 4);
        rw[u] = *(const float4*)(Wptr + (size_t)row * K + kq * 4);
    }

    for (int kt = 0; kt < K; kt += 16) {
        // store staged regs -> smem (transposed)
#pragma unroll
        for (int u = 0; u < 2; ++u) {
            int v = tid + u * 256;
            int row = v >> 2, kq = v & 3;
            As[kq * 4 + 0][row] = ra[u].x;  As[kq * 4 + 1][row] = ra[u].y;
            As[kq * 4 + 2][row] = ra[u].z;  As[kq * 4 + 3][row] = ra[u].w;
            Ws[kq * 4 + 0][row] = rw[u].x;  Ws[kq * 4 + 1][row] = rw[u].y;
            Ws[kq * 4 + 2][row] = rw[u].z;  Ws[kq * 4 + 3][row] = rw[u].w;
        }
        __syncthreads();

        if (kt + 16 < K) {
#pragma unroll
            for (int u = 0; u < 2; ++u) {
                int v = tid + u * 256;
                int row = v >> 2, kq = v & 3;
                ra[u] = *(const float4*)(Aptr + (size_t)row * K + (kt + 16) + kq * 4);
                rw[u] = *(const float4*)(Wptr + (size_t)row * K + (kt + 16) + kq * 4);
            }
        }

#pragma unroll
        for (int k = 0; k < 16; ++k) {
            float a[8], bb[8];
            *(float4*)&a[0]  = *(const float4*)&As[k][ty * 8];
            *(float4*)&a[4]  = *(const float4*)&As[k][ty * 8 + 4];
            *(float4*)&bb[0] = *(const float4*)&Ws[k][tx * 8];
            *(float4*)&bb[4] = *(const float4*)&Ws[k][tx * 8 + 4];
#pragma unroll
            for (int i = 0; i < 8; ++i)
#pragma unroll
                for (int j = 0; j < 8; ++j)
                    acc[i][j] = fmaf(a[i], bb[j], acc[i][j]);
        }
        __syncthreads();
    }

    // epilogue: bias + relu, vectorized stores
#pragma unroll
    for (int i = 0; i < 8; ++i) {
        int m = bm + ty * 8 + i;
        float* crow = Cout + (size_t)m * N + bn;
#pragma unroll
        for (int j = 0; j < 8; j += 4) {
            int n0 = bn + tx * 8 + j;
            float4 o;
            o.x = fmaxf(acc[i][j + 0] + bias[n0 + 0], 0.f);
            o.y = fmaxf(acc[i][j + 1] + bias[n0 + 1], 0.f);
            o.z = fmaxf(acc[i][j + 2] + bias[n0 + 2], 0.f);
            o.w = fmaxf(acc[i][j + 3] + bias[n0 + 3], 0.f);
            *(float4*)(crow + tx * 8 + j) = o;
        }
    }
}

// ---------------- M_part[b,h] = sum_{n in chunk} k[n]^T v[n] (per-head 64x64) ----------------
__global__ __launch_bounds__(256)
void kv_outer_partial()
{
    int bh = blockIdx.x;      // 0..63
    int part = blockIdx.y;    // 0..3
    int b = bh >> 3, h = bh & 7;

    __shared__ float Ks[32][64];
    __shared__ float Vs[32][64];

    int tid = threadIdx.x;
    int tx = tid & 15;   // e group (tx*4)
    int ty = tid >> 4;   // d group (ty*4)

    const float* kbase = g_k + ((size_t)b * 1024) * CDIM + h * 64;
    const float* vbase = g_v + ((size_t)b * 1024) * CDIM + h * 64;

    float acc[4][4];
#pragma unroll
    for (int i = 0; i < 4; ++i)
#pragma unroll
        for (int j = 0; j < 4; ++j) acc[i][j] = 0.f;

    int nbeg = part * 256, nend = nbeg + 256;
    for (int n0 = nbeg; n0 < nend; n0 += 32) {
#pragma unroll
        for (int u = 0; u < 2; ++u) {
            int v = tid + u * 256;
            int row = v >> 4, c4 = v & 15;
            *(float4*)&Ks[row][c4 * 4] = *(const float4*)(kbase + (size_t)(n0 + row) * CDIM + c4 * 4);
            *(float4*)&Vs[row][c4 * 4] = *(const float4*)(vbase + (size_t)(n0 + row) * CDIM + c4 * 4);
        }
        __syncthreads();
#pragma unroll
        for (int nn = 0; nn < 32; ++nn) {
            float4 kv = *(const float4*)&Ks[nn][ty * 4];
            float4 vv = *(const float4*)&Vs[nn][tx * 4];
            float ka[4] = {kv.x, kv.y, kv.z, kv.w};
            float va[4] = {vv.x, vv.y, vv.z, vv.w};
#pragma unroll
            for (int i = 0; i < 4; ++i)
#pragma unroll
                for (int j = 0; j < 4; ++j)
                    acc[i][j] = fmaf(ka[i], va[j], acc[i][j]);
        }
        __syncthreads();
    }

    float* mp = g_mpart + ((size_t)part * 64 + bh) * 4096;
#pragma unroll
    for (int i = 0; i < 4; ++i)
#pragma unroll
        for (int j = 0; j < 4; ++j)
            mp[(ty * 4 + i) * 64 + (tx * 4 + j)] = acc[i][j];
}

__global__ void kv_reduce()
{
    int i = blockIdx.x * blockDim.x + threadIdx.x;   // 64*4096 = 262144
    float s = g_mpart[i] + g_mpart[262144 + i] + g_mpart[2 * 262144 + i] + g_mpart[3 * 262144 + i];
    g_m[i] = s * SCALE_ATTN;
}

// ---------------- att[n, h*64+e] = relu( sum_d q[n, h*64+d] * M[b,h][d,e] ) ----------------
__global__ __launch_bounds__(256)
void qm_relu()
{
    int nt = blockIdx.x;   // 0..15 : 64-row tiles
    int h  = blockIdx.y;   // 0..7
    int b  = blockIdx.z;   // 0..7

    __shared__ float Qs[64][65];
    __shared__ float Ms[64][68];

    int tid = threadIdx.x;
    const float* qbase = g_q + ((size_t)(b * 1024 + nt * 64)) * CDIM + h * 64;
    const float* mbase = g_m + (size_t)(b * 8 + h) * 4096;

#pragma unroll
    for (int u = 0; u < 4; ++u) {
        int v = tid + u * 256;
        int row = v >> 4, c4 = v & 15;
        float4 t = *(const float4*)(qbase + (size_t)row * CDIM + c4 * 4);
        Qs[row][c4 * 4 + 0] = t.x; Qs[row][c4 * 4 + 1] = t.y;
        Qs[row][c4 * 4 + 2] = t.z; Qs[row][c4 * 4 + 3] = t.w;
        float4 mt = *(const float4*)(mbase + row * 64 + c4 * 4);
        *(float4*)&Ms[row][c4 * 4] = mt;
    }
    __syncthreads();

    int r = tid >> 2;          // 0..63
    int quarter = tid & 3;     // e-range quarter*16
    float acc[16];
#pragma unroll
    for (int e = 0; e < 16; ++e) acc[e] = 0.f;

#pragma unroll
    for (int d = 0; d < 64; ++d) {
        float qv = Qs[r][d];
#pragma unroll
        for (int e4 = 0; e4 < 4; ++e4) {
            float4 m = *(const float4*)&Ms[d][quarter * 16 + e4 * 4];
            acc[e4 * 4 + 0] = fmaf(qv, m.x, acc[e4 * 4 + 0]);
            acc[e4 * 4 + 1] = fmaf(qv, m.y, acc[e4 * 4 + 1]);
            acc[e4 * 4 + 2] = fmaf(qv, m.z, acc[e4 * 4 + 2]);
            acc[e4 * 4 + 3] = fmaf(qv, m.w, acc[e4 * 4 + 3]);
        }
    }

    float* obase = g_att + ((size_t)(b * 1024 + nt * 64 + r)) * CDIM + h * 64 + quarter * 16;
#pragma unroll
    for (int e4 = 0; e4 < 4; ++e4) {
        float4 o;
        o.x = fmaxf(acc[e4 * 4 + 0], 0.f);
        o.y = fmaxf(acc[e4 * 4 + 1], 0.f);
        o.z = fmaxf(acc[e4 * 4 + 2], 0.f);
        o.w = fmaxf(acc[e4 * 4 + 3], 0.f);
        *(float4*)(obase + e4 * 4) = o;
    }
}

// ---------------- host launch ----------------
extern "C" void kernel_launch(void* const* d_in, const int* in_sizes, int n_in,
                              void* d_out, int out_size)
{
    (void)in_sizes; (void)n_in; (void)out_size;
    const float* x = (const float*)d_in[0];
    // per-set params: w,b,g,beta,mu,var at d_in[1+6s .. 6+6s], sets: 0=q,1=k,2=v,3=p
    for (int s = 0; s < 4; ++s) {
        const float* w    = (const float*)d_in[1 + 6 * s + 0];
        const float* b    = (const float*)d_in[1 + 6 * s + 1];
        const float* g    = (const float*)d_in[1 + 6 * s + 2];
        const float* beta = (const float*)d_in[1 + 6 * s + 3];
        const float* mu   = (const float*)d_in[1 + 6 * s + 4];
        const float* var  = (const float*)d_in[1 + 6 * s + 5];
        fold_kernel<<<1024, 256>>>(w, b, g, beta, mu, var, s);
    }

    dim3 gemmGrid(CDIM / 128, MROWS / 128);   // (4, 64)
    // q, k, v projections from x
    gemm_bias_relu<<<gemmGrid, 256>>>(x, nullptr, 0, 0, 0, MROWS, CDIM, CDIM);
    gemm_bias_relu<<<gemmGrid, 256>>>(x, nullptr, 0, 1, 1, MROWS, CDIM, CDIM);
    gemm_bias_relu<<<gemmGrid, 256>>>(x, nullptr, 0, 2, 2, MROWS, CDIM, CDIM);

    // attention (linear, no softmax): M = scale * k^T v per (b,h); att = relu(q @ M)
    kv_outer_partial<<<dim3(64, 4), 256>>>();
    kv_reduce<<<1024, 256>>>();
    qm_relu<<<dim3(16, 8, 8), 256>>>();

    // final projection -> d_out
    gemm_bias_relu<<<gemmGrid, 256>>>(nullptr, (float*)d_out, 1, 3, 3, MROWS, CDIM, CDIM);
}

// round 3
// speedup vs baseline: 1.7136x; 1.7136x over previous
#include <cuda_runtime.h>
#include <cuda_bf16.h>
#include <cstdint>

#define EPS_BN 1e-5f
#define SCALE_ATTN 0.125f
#define CDIM 512
#define MROWS 8192   // B*N

// ============================ scratch (static device mem) ============================
__device__ __align__(16) __nv_bfloat16 g_xh[MROWS*CDIM], g_xl[MROWS*CDIM];
__device__ __align__(16) __nv_bfloat16 g_atth[MROWS*CDIM], g_attl[MROWS*CDIM];
__device__ __align__(16) __nv_bfloat16 g_whq[CDIM*CDIM], g_wlq[CDIM*CDIM];
__device__ __align__(16) __nv_bfloat16 g_whk[CDIM*CDIM], g_wlk[CDIM*CDIM];
__device__ __align__(16) __nv_bfloat16 g_whv[CDIM*CDIM], g_wlv[CDIM*CDIM];
__device__ __align__(16) __nv_bfloat16 g_whp[CDIM*CDIM], g_wlp[CDIM*CDIM];
__device__ float g_bq[CDIM], g_bk[CDIM], g_bv[CDIM], g_bp[CDIM];
__device__ __align__(16) float g_q[MROWS*CDIM], g_k[MROWS*CDIM], g_v[MROWS*CDIM];
__device__ __align__(16) float g_att[MROWS*CDIM];
__device__ float g_m[64*64*64];
__device__ float g_mpart[4*64*64*64];

// ============================ portable PTX helpers ============================
__device__ __forceinline__ uint32_t smem_u32(const void* p) {
    uint32_t a;
    asm("{ .reg .u64 t; cvta.to.shared.u64 t, %1; cvt.u32.u64 %0, t; }" : "=r"(a) : "l"(p));
    return a;
}
__device__ __forceinline__ void cp16(uint32_t saddr, const void* g) {
    asm volatile("cp.async.cg.shared.global [%0], [%1], 16;" :: "r"(saddr), "l"(g) : "memory");
}
__device__ __forceinline__ void cp_commit() {
    asm volatile("cp.async.commit_group;" ::: "memory");
}
template <int N> __device__ __forceinline__ void cp_wait() {
    asm volatile("cp.async.wait_group %0;" :: "n"(N) : "memory");
}
__device__ __forceinline__ void ldsm4(uint32_t* r, uint32_t addr) {
    asm volatile("ldmatrix.sync.aligned.m8n8.x4.shared.b16 {%0,%1,%2,%3}, [%4];"
                 : "=r"(r[0]), "=r"(r[1]), "=r"(r[2]), "=r"(r[3]) : "r"(addr));
}
__device__ __forceinline__ void mma_bf16(float* c, const uint32_t* a, uint32_t b0, uint32_t b1) {
    asm volatile(
        "mma.sync.aligned.m16n8k16.row.col.f32.bf16.bf16.f32 "
        "{%0,%1,%2,%3}, {%4,%5,%6,%7}, {%8,%9}, {%0,%1,%2,%3};"
        : "+f"(c[0]), "+f"(c[1]), "+f"(c[2]), "+f"(c[3])
        : "r"(a[0]), "r"(a[1]), "r"(a[2]), "r"(a[3]), "r"(b0), "r"(b1));
}

// ============================ fold BN into bf16-split weights ============================
__global__ void fold_split(const float* __restrict__ w, const float* __restrict__ b,
                           const float* __restrict__ g, const float* __restrict__ beta,
                           const float* __restrict__ mu, const float* __restrict__ var, int s)
{
    __nv_bfloat16* wh = (s == 0) ? g_whq : (s == 1) ? g_whk : (s == 2) ? g_whv : g_whp;
    __nv_bfloat16* wl = (s == 0) ? g_wlq : (s == 1) ? g_wlk : (s == 2) ? g_wlv : g_wlp;
    float* bias = (s == 0) ? g_bq : (s == 1) ? g_bk : (s == 2) ? g_bv : g_bp;
    int i = blockIdx.x * blockDim.x + threadIdx.x;   // 512*512
    int d = i >> 9;
    float sc = g[d] * rsqrtf(var[d] + EPS_BN);
    float wv = w[i] * sc;
    __nv_bfloat16 h = __float2bfloat16(wv);
    wh[i] = h;
    wl[i] = __float2bfloat16(wv - __bfloat162float(h));
    if ((i & 511) == 0) bias[d] = (b[d] - mu[d]) * sc + beta[d];
}

// ============================ fp32 -> bf16 hi/lo split ============================
__global__ void split_bf16(const float* __restrict__ in, int sel, int n4)
{
    __nv_bfloat16* hi = sel ? g_atth : g_xh;
    __nv_bfloat16* lo = sel ? g_attl : g_xl;
    const float* src = sel ? g_att : in;
    int i = blockIdx.x * blockDim.x + threadIdx.x;
    if (i >= n4) return;
    float4 v = ((const float4*)src)[i];
    __nv_bfloat16 h0 = __float2bfloat16(v.x), h1 = __float2bfloat16(v.y);
    __nv_bfloat16 h2 = __float2bfloat16(v.z), h3 = __float2bfloat16(v.w);
    __nv_bfloat162 hh0; hh0.x = h0; hh0.y = h1;
    __nv_bfloat162 hh1; hh1.x = h2; hh1.y = h3;
    ((__nv_bfloat162*)hi)[i * 2 + 0] = hh0;
    ((__nv_bfloat162*)hi)[i * 2 + 1] = hh1;
    __nv_bfloat162 ll0, ll1;
    ll0.x = __float2bfloat16(v.x - __bfloat162float(h0));
    ll0.y = __float2bfloat16(v.y - __bfloat162float(h1));
    ll1.x = __float2bfloat16(v.z - __bfloat162float(h2));
    ll1.y = __float2bfloat16(v.w - __bfloat162float(h3));
    ((__nv_bfloat162*)lo)[i * 2 + 0] = ll0;
    ((__nv_bfloat162*)lo)[i * 2 + 1] = ll1;
}

// ============================ HMMA GEMM: C = relu(A @ W^T + bias) ============================
// A,W bf16-split hi/lo, K-major [rows,512]. CTA tile 128x128, BK=32, 8 warps (64x32 each).
// 3-product compensation: AhWh + AhWl + AlWh (fp32 acc).
#define BK 32
#define NSTAGE (CDIM / BK)        // 16
#define TPAD 40                   // bf16 row stride in smem (80B: conflict-free LDSM)
#define TBYTES (128 * TPAD * 2)   // 10240 per tensor tile
#define BUFB (4 * TBYTES)         // Ah, Al, Wh, Wl
#define GEMM_SMEM (2 * BUFB)      // 81920

__global__ __launch_bounds__(256, 1)
void gemm_tc(float* __restrict__ Cext, int asel, int wsel, int osel)
{
    extern __shared__ char smem[];
    const __nv_bfloat16* Ah = asel ? g_atth : g_xh;
    const __nv_bfloat16* Al = asel ? g_attl : g_xl;
    const __nv_bfloat16* Wh = (wsel == 0) ? g_whq : (wsel == 1) ? g_whk : (wsel == 2) ? g_whv : g_whp;
    const __nv_bfloat16* Wl = (wsel == 0) ? g_wlq : (wsel == 1) ? g_wlk : (wsel == 2) ? g_wlv : g_wlp;
    const float* bias = (wsel == 0) ? g_bq : (wsel == 1) ? g_bk : (wsel == 2) ? g_bv : g_bp;
    float* C = (osel == 0) ? g_q : (osel == 1) ? g_k : (osel == 2) ? g_v : Cext;

    const uint32_t sb = smem_u32(smem);
    const int tid = threadIdx.x;
    const int wid = tid >> 5, lane = tid & 31;
    const int wm = wid & 1, wn = wid >> 1;         // warp grid 2(m) x 4(n)
    const int bn = blockIdx.x * 128, bm = blockIdx.y * 128;

    const __nv_bfloat16* src[4] = {
        Ah + (size_t)bm * CDIM, Al + (size_t)bm * CDIM,
        Wh + (size_t)bn * CDIM, Wl + (size_t)bn * CDIM };

    // per-thread gmem->smem mapping: 8 chunks of 16B
    // idx = tid + t*256 ; tensor = idx>>9 ; v = idx&511 ; row = v>>2 ; chunk = v&3
    auto load_stage = [&](int s, int buf) {
        uint32_t sbase = sb + buf * BUFB;
#pragma unroll
        for (int t = 0; t < 8; ++t) {
            int idx = tid + t * 256;
            int ten = idx >> 9;
            int v = idx & 511;
            int row = v >> 2, ch = v & 3;
            const __nv_bfloat16* g = src[ten] + (size_t)row * CDIM + s * BK + ch * 8;
            cp16(sbase + ten * TBYTES + row * (TPAD * 2) + ch * 16, g);
        }
        cp_commit();
    };

    float acc[4][4][4];
#pragma unroll
    for (int i = 0; i < 4; ++i)
#pragma unroll
        for (int j = 0; j < 4; ++j)
#pragma unroll
            for (int k = 0; k < 4; ++k) acc[i][j][k] = 0.f;

    // LDSM per-lane address components
    const int g8 = lane >> 3;          // 0..3
    const int l8 = lane & 7;           // 0..7
    // A frag: row_off = (g8&1)*8 + l8 ; k_off = (g8>>1)*8
    const int a_row = (g8 & 1) * 8 + l8;
    const int a_k = (g8 >> 1) * 8;
    // W frag: n_off = (g8>>1)*8 + l8 ; k_off = (g8&1)*8
    const int w_row = (g8 >> 1) * 8 + l8;
    const int w_k = (g8 & 1) * 8;

    load_stage(0, 0);

    for (int s = 0; s < NSTAGE; ++s) {
        if (s + 1 < NSTAGE) load_stage(s + 1, (s + 1) & 1);
        if (s + 1 < NSTAGE) cp_wait<1>(); else cp_wait<0>();
        __syncthreads();

        const uint32_t base = sb + (s & 1) * BUFB;
#pragma unroll
        for (int kk = 0; kk < BK; kk += 16) {
            // W fragments: 2 LDSM.x4 per tensor (each covers n16 x k16)
            uint32_t whf[2][4], wlf[2][4];
#pragma unroll
            for (int j = 0; j < 2; ++j) {
                int nrow = wn * 32 + j * 16 + w_row;
                uint32_t off = nrow * (TPAD * 2) + (kk + w_k) * 2;
                ldsm4(whf[j], base + 2 * TBYTES + off);
                ldsm4(wlf[j], base + 3 * TBYTES + off);
            }
#pragma unroll
            for (int mi = 0; mi < 4; ++mi) {
                uint32_t ahf[4], alf[4];
                int mrow = wm * 64 + mi * 16 + a_row;
                uint32_t off = mrow * (TPAD * 2) + (kk + a_k) * 2;
                ldsm4(ahf, base + 0 * TBYTES + off);
                ldsm4(alf, base + 1 * TBYTES + off);
#pragma unroll
                for (int j = 0; j < 2; ++j) {
#pragma unroll
                    for (int jj = 0; jj < 2; ++jj) {
                        int nj = j * 2 + jj;
                        uint32_t b0 = whf[j][jj * 2 + 0], b1 = whf[j][jj * 2 + 1];
                        uint32_t c0 = wlf[j][jj * 2 + 0], c1 = wlf[j][jj * 2 + 1];
                        mma_bf16(acc[mi][nj], ahf, b0, b1);   // Ah*Wh
                        mma_bf16(acc[mi][nj], ahf, c0, c1);   // Ah*Wl
                        mma_bf16(acc[mi][nj], alf, b0, b1);   // Al*Wh
                    }
                }
            }
        }
        __syncthreads();
    }

    // epilogue: bias + relu
    const int r_in = lane >> 2;
    const int c_in = (lane & 3) * 2;
#pragma unroll
    for (int mi = 0; mi < 4; ++mi) {
        int r0 = bm + wm * 64 + mi * 16 + r_in;
#pragma unroll
        for (int nj = 0; nj < 4; ++nj) {
            int c0 = bn + wn * 32 + nj * 8 + c_in;
            float b0 = bias[c0], b1 = bias[c0 + 1];
            float2 lo, hi;
            lo.x = fmaxf(acc[mi][nj][0] + b0, 0.f);
            lo.y = fmaxf(acc[mi][nj][1] + b1, 0.f);
            hi.x = fmaxf(acc[mi][nj][2] + b0, 0.f);
            hi.y = fmaxf(acc[mi][nj][3] + b1, 0.f);
            *(float2*)(C + (size_t)r0 * CDIM + c0) = lo;
            *(float2*)(C + (size_t)(r0 + 8) * CDIM + c0) = hi;
        }
    }
}

// ============================ attention middle (fp32 SIMT, cheap) ============================
__global__ __launch_bounds__(256)
void kv_outer_partial()
{
    int bh = blockIdx.x, part = blockIdx.y;
    int b = bh >> 3, h = bh & 7;
    __shared__ float Ks[32][64];
    __shared__ float Vs[32][64];
    int tid = threadIdx.x;
    int tx = tid & 15, ty = tid >> 4;
    const float* kbase = g_k + ((size_t)b * 1024) * CDIM + h * 64;
    const float* vbase = g_v + ((size_t)b * 1024) * CDIM + h * 64;
    float acc[4][4];
#pragma unroll
    for (int i = 0; i < 4; ++i)
#pragma unroll
        for (int j = 0; j < 4; ++j) acc[i][j] = 0.f;
    int nbeg = part * 256, nend = nbeg + 256;
    for (int n0 = nbeg; n0 < nend; n0 += 32) {
#pragma unroll
        for (int u = 0; u < 2; ++u) {
            int v = tid + u * 256;
            int r = v >> 4, c4 = v & 15;
            *(float4*)&Ks[r][c4 * 4] = *(const float4*)(kbase + (size_t)(n0 + r) * CDIM + c4 * 4);
            *(float4*)&Vs[r][c4 * 4] = *(const float4*)(vbase + (size_t)(n0 + r) * CDIM + c4 * 4);
        }
        __syncthreads();
#pragma unroll
        for (int nn = 0; nn < 32; ++nn) {
            float4 kv = *(const float4*)&Ks[nn][ty * 4];
            float4 vv = *(const float4*)&Vs[nn][tx * 4];
            float ka[4] = {kv.x, kv.y, kv.z, kv.w};
            float va[4] = {vv.x, vv.y, vv.z, vv.w};
#pragma unroll
            for (int i = 0; i < 4; ++i)
#pragma unroll
                for (int j = 0; j < 4; ++j)
                    acc[i][j] = fmaf(ka[i], va[j], acc[i][j]);
        }
        __syncthreads();
    }
    float* mp = g_mpart + ((size_t)part * 64 + bh) * 4096;
#pragma unroll
    for (int i = 0; i < 4; ++i)
#pragma unroll
        for (int j = 0; j < 4; ++j)
            mp[(ty * 4 + i) * 64 + (tx * 4 + j)] = acc[i][j];
}

__global__ void kv_reduce()
{
    int i = blockIdx.x * blockDim.x + threadIdx.x;
    float s = g_mpart[i] + g_mpart[262144 + i] + g_mpart[2 * 262144 + i] + g_mpart[3 * 262144 + i];
    g_m[i] = s * SCALE_ATTN;
}

__global__ __launch_bounds__(256)
void qm_relu()
{
    int nt = blockIdx.x, h = blockIdx.y, b = blockIdx.z;
    __shared__ float Qs[64][65];
    __shared__ float Ms[64][68];
    int tid = threadIdx.x;
    const float* qbase = g_q + ((size_t)(b * 1024 + nt * 64)) * CDIM + h * 64;
    const float* mbase = g_m + (size_t)(b * 8 + h) * 4096;
#pragma unroll
    for (int u = 0; u < 4; ++u) {
        int v = tid + u * 256;
        int r = v >> 4, c4 = v & 15;
        float4 t = *(const float4*)(qbase + (size_t)r * CDIM + c4 * 4);
        Qs[r][c4 * 4 + 0] = t.x; Qs[r][c4 * 4 + 1] = t.y;
        Qs[r][c4 * 4 + 2] = t.z; Qs[r][c4 * 4 + 3] = t.w;
        *(float4*)&Ms[r][c4 * 4] = *(const float4*)(mbase + r * 64 + c4 * 4);
    }
    __syncthreads();
    int r = tid >> 2, quarter = tid & 3;
    float acc[16];
#pragma unroll
    for (int e = 0; e < 16; ++e) acc[e] = 0.f;
#pragma unroll
    for (int d = 0; d < 64; ++d) {
        float qv = Qs[r][d];
#pragma unroll
        for (int e4 = 0; e4 < 4; ++e4) {
            float4 m = *(const float4*)&Ms[d][quarter * 16 + e4 * 4];
            acc[e4 * 4 + 0] = fmaf(qv, m.x, acc[e4 * 4 + 0]);
            acc[e4 * 4 + 1] = fmaf(qv, m.y, acc[e4 * 4 + 1]);
            acc[e4 * 4 + 2] = fmaf(qv, m.z, acc[e4 * 4 + 2]);
            acc[e4 * 4 + 3] = fmaf(qv, m.w, acc[e4 * 4 + 3]);
        }
    }
    float* obase = g_att + ((size_t)(b * 1024 + nt * 64 + r)) * CDIM + h * 64 + quarter * 16;
#pragma unroll
    for (int e4 = 0; e4 < 4; ++e4) {
        float4 o;
        o.x = fmaxf(acc[e4 * 4 + 0], 0.f);
        o.y = fmaxf(acc[e4 * 4 + 1], 0.f);
        o.z = fmaxf(acc[e4 * 4 + 2], 0.f);
        o.w = fmaxf(acc[e4 * 4 + 3], 0.f);
        *(float4*)(obase + e4 * 4) = o;
    }
}

// ============================ host launch ============================
extern "C" void kernel_launch(void* const* d_in, const int* in_sizes, int n_in,
                              void* d_out, int out_size)
{
    (void)in_sizes; (void)n_in; (void)out_size;
    const float* x = (const float*)d_in[0];

    cudaFuncSetAttribute(gemm_tc, cudaFuncAttributeMaxDynamicSharedMemorySize, GEMM_SMEM);

    for (int s = 0; s < 4; ++s) {
        const float* w    = (const float*)d_in[1 + 6 * s + 0];
        const float* b    = (const float*)d_in[1 + 6 * s + 1];
        const float* g    = (const float*)d_in[1 + 6 * s + 2];
        const float* beta = (const float*)d_in[1 + 6 * s + 3];
        const float* mu   = (const float*)d_in[1 + 6 * s + 4];
        const float* var  = (const float*)d_in[1 + 6 * s + 5];
        fold_split<<<1024, 256>>>(w, b, g, beta, mu, var, s);
    }

    int n4 = MROWS * CDIM / 4;
    split_bf16<<<(n4 + 255) / 256, 256>>>(x, 0, n4);

    dim3 gemmGrid(CDIM / 128, MROWS / 128);   // (4, 64)
    gemm_tc<<<gemmGrid, 256, GEMM_SMEM>>>(nullptr, 0, 0, 0);  // q
    gemm_tc<<<gemmGrid, 256, GEMM_SMEM>>>(nullptr, 0, 1, 1);  // k
    gemm_tc<<<gemmGrid, 256, GEMM_SMEM>>>(nullptr, 0, 2, 2);  // v

    kv_outer_partial<<<dim3(64, 4), 256>>>();
    kv_reduce<<<1024, 256>>>();
    qm_relu<<<dim3(16, 8, 8), 256>>>();

    split_bf16<<<(n4 + 255) / 256, 256>>>(nullptr, 1, n4);    // att -> bf16 hi/lo
    gemm_tc<<<gemmGrid, 256, GEMM_SMEM>>>((float*)d_out, 1, 3, 3);
}

// round 4
// speedup vs baseline: 1.9013x; 1.1095x over previous
#include <cuda_runtime.h>
#include <cuda_bf16.h>
#include <cstdint>

#define EPS_BN 1e-5f
#define SCALE_ATTN 0.125f
#define CDIM 512
#define MROWS 8192   // B*N

// ============================ scratch (static device mem) ============================
__device__ __align__(16) __nv_bfloat16 g_xh[MROWS*CDIM], g_xl[MROWS*CDIM];
__device__ __align__(16) __nv_bfloat16 g_atth[MROWS*CDIM], g_attl[MROWS*CDIM];
__device__ __align__(16) __nv_bfloat16 g_whq[CDIM*CDIM], g_wlq[CDIM*CDIM];
__device__ __align__(16) __nv_bfloat16 g_whk[CDIM*CDIM], g_wlk[CDIM*CDIM];
__device__ __align__(16) __nv_bfloat16 g_whv[CDIM*CDIM], g_wlv[CDIM*CDIM];
__device__ __align__(16) __nv_bfloat16 g_whp[CDIM*CDIM], g_wlp[CDIM*CDIM];
__device__ float g_bq[CDIM], g_bk[CDIM], g_bv[CDIM], g_bp[CDIM];
__device__ __align__(16) float g_q[MROWS*CDIM], g_k[MROWS*CDIM], g_v[MROWS*CDIM];
__device__ float g_mpart[4*64*64*64];

// ============================ portable PTX helpers ============================
__device__ __forceinline__ uint32_t smem_u32(const void* p) {
    uint32_t a;
    asm("{ .reg .u64 t; cvta.to.shared.u64 t, %1; cvt.u32.u64 %0, t; }" : "=r"(a) : "l"(p));
    return a;
}
__device__ __forceinline__ void cp16(uint32_t saddr, const void* g) {
    asm volatile("cp.async.cg.shared.global [%0], [%1], 16;" :: "r"(saddr), "l"(g) : "memory");
}
__device__ __forceinline__ void cp_commit() {
    asm volatile("cp.async.commit_group;" ::: "memory");
}
template <int N> __device__ __forceinline__ void cp_wait() {
    asm volatile("cp.async.wait_group %0;" :: "n"(N) : "memory");
}
__device__ __forceinline__ void ldsm4(uint32_t* r, uint32_t addr) {
    asm volatile("ldmatrix.sync.aligned.m8n8.x4.shared.b16 {%0,%1,%2,%3}, [%4];"
                 : "=r"(r[0]), "=r"(r[1]), "=r"(r[2]), "=r"(r[3]) : "r"(addr));
}
__device__ __forceinline__ void mma_bf16(float* c, const uint32_t* a, uint32_t b0, uint32_t b1) {
    asm volatile(
        "mma.sync.aligned.m16n8k16.row.col.f32.bf16.bf16.f32 "
        "{%0,%1,%2,%3}, {%4,%5,%6,%7}, {%8,%9}, {%0,%1,%2,%3};"
        : "+f"(c[0]), "+f"(c[1]), "+f"(c[2]), "+f"(c[3])
        : "r"(a[0]), "r"(a[1]), "r"(a[2]), "r"(a[3]), "r"(b0), "r"(b1));
}

// ============================ fused BN fold for all 4 weight sets ============================
__global__ void fold_split_all(
    const float* __restrict__ w0, const float* __restrict__ b0, const float* __restrict__ g0,
    const float* __restrict__ be0, const float* __restrict__ mu0, const float* __restrict__ va0,
    const float* __restrict__ w1, const float* __restrict__ b1, const float* __restrict__ g1,
    const float* __restrict__ be1, const float* __restrict__ mu1, const float* __restrict__ va1,
    const float* __restrict__ w2, const float* __restrict__ b2, const float* __restrict__ g2,
    const float* __restrict__ be2, const float* __restrict__ mu2, const float* __restrict__ va2,
    const float* __restrict__ w3, const float* __restrict__ b3, const float* __restrict__ g3,
    const float* __restrict__ be3, const float* __restrict__ mu3, const float* __restrict__ va3)
{
    int gi = blockIdx.x * blockDim.x + threadIdx.x;   // 4 * 262144
    int s = gi >> 18;
    int i = gi & 262143;
    const float *w, *b, *g, *beta, *mu, *var;
    __nv_bfloat16 *wh, *wl;
    float* bias;
    if (s == 0) { w=w0;b=b0;g=g0;beta=be0;mu=mu0;var=va0; wh=g_whq;wl=g_wlq;bias=g_bq; }
    else if (s == 1) { w=w1;b=b1;g=g1;beta=be1;mu=mu1;var=va1; wh=g_whk;wl=g_wlk;bias=g_bk; }
    else if (s == 2) { w=w2;b=b2;g=g2;beta=be2;mu=mu2;var=va2; wh=g_whv;wl=g_wlv;bias=g_bv; }
    else { w=w3;b=b3;g=g3;beta=be3;mu=mu3;var=va3; wh=g_whp;wl=g_wlp;bias=g_bp; }
    int d = i >> 9;
    float sc = g[d] * rsqrtf(var[d] + EPS_BN);
    float wv = w[i] * sc;
    __nv_bfloat16 h = __float2bfloat16(wv);
    wh[i] = h;
    wl[i] = __float2bfloat16(wv - __bfloat162float(h));
    if ((i & 511) == 0) bias[d] = (b[d] - mu[d]) * sc + beta[d];
}

// ============================ fp32 -> bf16 hi/lo split (x only) ============================
__global__ void split_bf16_x(const float* __restrict__ src, int n4)
{
    int i = blockIdx.x * blockDim.x + threadIdx.x;
    if (i >= n4) return;
    float4 v = ((const float4*)src)[i];
    __nv_bfloat16 h0 = __float2bfloat16(v.x), h1 = __float2bfloat16(v.y);
    __nv_bfloat16 h2 = __float2bfloat16(v.z), h3 = __float2bfloat16(v.w);
    __nv_bfloat162 hh0; hh0.x = h0; hh0.y = h1;
    __nv_bfloat162 hh1; hh1.x = h2; hh1.y = h3;
    ((__nv_bfloat162*)g_xh)[i * 2 + 0] = hh0;
    ((__nv_bfloat162*)g_xh)[i * 2 + 1] = hh1;
    __nv_bfloat162 ll0, ll1;
    ll0.x = __float2bfloat16(v.x - __bfloat162float(h0));
    ll0.y = __float2bfloat16(v.y - __bfloat162float(h1));
    ll1.x = __float2bfloat16(v.z - __bfloat162float(h2));
    ll1.y = __float2bfloat16(v.w - __bfloat162float(h3));
    ((__nv_bfloat162*)g_xl)[i * 2 + 0] = ll0;
    ((__nv_bfloat162*)g_xl)[i * 2 + 1] = ll1;
}

// ============================ HMMA GEMM v2: C = relu(A @ W^T + bias) ============================
// CTA tile 128(m) x 256(n), BK=32, 512 threads (16 warps, 64x32 warp tiles), 3-stage cp.async.
// Grid (2, 64) = 128 CTAs = one wave on 148+ SMs.
#define BK 32
#define NSTAGE (CDIM / BK)          // 16
#define RPITCH 80                   // smem row pitch bytes (64B data + 16B pad)
#define A_TB (128 * RPITCH)         // 10240
#define W_TB (256 * RPITCH)         // 20480
#define STAGEB (2 * A_TB + 2 * W_TB)// 61440: [Ah, Al, Wh, Wl]
#define GEMM_SMEM (3 * STAGEB)      // 184320

__global__ __launch_bounds__(512, 1)
void gemm_tc(float* __restrict__ Cext, int asel, int wsel, int osel)
{
    extern __shared__ char smem[];
    const __nv_bfloat16* Ah = asel ? g_atth : g_xh;
    const __nv_bfloat16* Al = asel ? g_attl : g_xl;
    const __nv_bfloat16* Wh = (wsel == 0) ? g_whq : (wsel == 1) ? g_whk : (wsel == 2) ? g_whv : g_whp;
    const __nv_bfloat16* Wl = (wsel == 0) ? g_wlq : (wsel == 1) ? g_wlk : (wsel == 2) ? g_wlv : g_wlp;
    const float* bias = (wsel == 0) ? g_bq : (wsel == 1) ? g_bk : (wsel == 2) ? g_bv : g_bp;
    float* C = (osel == 0) ? g_q : (osel == 1) ? g_k : (osel == 2) ? g_v : Cext;

    const uint32_t sb = smem_u32(smem);
    const int tid = threadIdx.x;
    const int wid = tid >> 5, lane = tid & 31;
    const int wm = wid & 1, wn = wid >> 1;         // 2(m) x 8(n) warps
    const int bn = blockIdx.x * 256, bm = blockIdx.y * 128;

    const __nv_bfloat16* srcA[2] = { Ah + (size_t)bm * CDIM, Al + (size_t)bm * CDIM };
    const __nv_bfloat16* srcW[2] = { Wh + (size_t)bn * CDIM, Wl + (size_t)bn * CDIM };

    // 3072 16B-chunks per stage, 6 per thread
    auto load_stage = [&](int s, int buf) {
        uint32_t sbase = sb + buf * STAGEB;
        int kof = s * BK;
#pragma unroll
        for (int t = 0; t < 6; ++t) {
            int idx = tid + t * 512;
            if (idx < 1024) {
                int ten = idx >> 9, v = idx & 511;
                int row = v >> 2, ch = v & 3;
                cp16(sbase + ten * A_TB + row * RPITCH + ch * 16,
                     srcA[ten] + (size_t)row * CDIM + kof + ch * 8);
            } else {
                int j = idx - 1024;
                int ten = j >> 10, v = j & 1023;
                int row = v >> 2, ch = v & 3;
                cp16(sbase + 2 * A_TB + ten * W_TB + row * RPITCH + ch * 16,
                     srcW[ten] + (size_t)row * CDIM + kof + ch * 8);
            }
        }
        cp_commit();
    };

    float acc[4][4][4];
#pragma unroll
    for (int i = 0; i < 4; ++i)
#pragma unroll
        for (int j = 0; j < 4; ++j)
#pragma unroll
            for (int k = 0; k < 4; ++k) acc[i][j][k] = 0.f;

    const int g8 = lane >> 3, l8 = lane & 7;
    const int a_row = (g8 & 1) * 8 + l8;
    const int a_k = (g8 >> 1) * 8;
    const int w_row = (g8 >> 1) * 8 + l8;
    const int w_k = (g8 & 1) * 8;

    load_stage(0, 0);
    load_stage(1, 1);

    for (int s = 0; s < NSTAGE; ++s) {
        if (s + 2 < NSTAGE) load_stage(s + 2, (s + 2) % 3);
        if (s + 2 < NSTAGE)      cp_wait<2>();
        else if (s + 1 < NSTAGE) cp_wait<1>();
        else                     cp_wait<0>();
        __syncthreads();

        const uint32_t base = sb + (s % 3) * STAGEB;
#pragma unroll
        for (int kk = 0; kk < BK; kk += 16) {
            uint32_t whf[2][4], wlf[2][4];
#pragma unroll
            for (int j = 0; j < 2; ++j) {
                int nrow = wn * 32 + j * 16 + w_row;
                uint32_t off = nrow * RPITCH + (kk + w_k) * 2;
                ldsm4(whf[j], base + 2 * A_TB + off);
                ldsm4(wlf[j], base + 2 * A_TB + W_TB + off);
            }
#pragma unroll
            for (int mi = 0; mi < 4; ++mi) {
                uint32_t ahf[4], alf[4];
                int mrow = wm * 64 + mi * 16 + a_row;
                uint32_t off = mrow * RPITCH + (kk + a_k) * 2;
                ldsm4(ahf, base + off);
                ldsm4(alf, base + A_TB + off);
#pragma unroll
                for (int j = 0; j < 2; ++j) {
#pragma unroll
                    for (int jj = 0; jj < 2; ++jj) {
                        int nj = j * 2 + jj;
                        uint32_t b0 = whf[j][jj * 2 + 0], b1 = whf[j][jj * 2 + 1];
                        uint32_t c0 = wlf[j][jj * 2 + 0], c1 = wlf[j][jj * 2 + 1];
                        mma_bf16(acc[mi][nj], ahf, b0, b1);
                        mma_bf16(acc[mi][nj], ahf, c0, c1);
                        mma_bf16(acc[mi][nj], alf, b0, b1);
                    }
                }
            }
        }
        __syncthreads();
    }

    const int r_in = lane >> 2;
    const int c_in = (lane & 3) * 2;
#pragma unroll
    for (int mi = 0; mi < 4; ++mi) {
        int r0 = bm + wm * 64 + mi * 16 + r_in;
#pragma unroll
        for (int nj = 0; nj < 4; ++nj) {
            int c0 = bn + wn * 32 + nj * 8 + c_in;
            float b0 = bias[c0], b1 = bias[c0 + 1];
            float2 lo, hi;
            lo.x = fmaxf(acc[mi][nj][0] + b0, 0.f);
            lo.y = fmaxf(acc[mi][nj][1] + b1, 0.f);
            hi.x = fmaxf(acc[mi][nj][2] + b0, 0.f);
            hi.y = fmaxf(acc[mi][nj][3] + b1, 0.f);
            *(float2*)(C + (size_t)r0 * CDIM + c0) = lo;
            *(float2*)(C + (size_t)(r0 + 8) * CDIM + c0) = hi;
        }
    }
}

// ============================ attention middle ============================
__global__ __launch_bounds__(256)
void kv_outer_partial()
{
    int bh = blockIdx.x, part = blockIdx.y;
    int b = bh >> 3, h = bh & 7;
    __shared__ float Ks[32][64];
    __shared__ float Vs[32][64];
    int tid = threadIdx.x;
    int tx = tid & 15, ty = tid >> 4;
    const float* kbase = g_k + ((size_t)b * 1024) * CDIM + h * 64;
    const float* vbase = g_v + ((size_t)b * 1024) * CDIM + h * 64;
    float acc[4][4];
#pragma unroll
    for (int i = 0; i < 4; ++i)
#pragma unroll
        for (int j = 0; j < 4; ++j) acc[i][j] = 0.f;
    int nbeg = part * 256, nend = nbeg + 256;
    for (int n0 = nbeg; n0 < nend; n0 += 32) {
#pragma unroll
        for (int u = 0; u < 2; ++u) {
            int v = tid + u * 256;
            int r = v >> 4, c4 = v & 15;
            *(float4*)&Ks[r][c4 * 4] = *(const float4*)(kbase + (size_t)(n0 + r) * CDIM + c4 * 4);
            *(float4*)&Vs[r][c4 * 4] = *(const float4*)(vbase + (size_t)(n0 + r) * CDIM + c4 * 4);
        }
        __syncthreads();
#pragma unroll
        for (int nn = 0; nn < 32; ++nn) {
            float4 kv = *(const float4*)&Ks[nn][ty * 4];
            float4 vv = *(const float4*)&Vs[nn][tx * 4];
            float ka[4] = {kv.x, kv.y, kv.z, kv.w};
            float va[4] = {vv.x, vv.y, vv.z, vv.w};
#pragma unroll
            for (int i = 0; i < 4; ++i)
#pragma unroll
                for (int j = 0; j < 4; ++j)
                    acc[i][j] = fmaf(ka[i], va[j], acc[i][j]);
        }
        __syncthreads();
    }
    float* mp = g_mpart + ((size_t)part * 64 + bh) * 4096;
#pragma unroll
    for (int i = 0; i < 4; ++i)
#pragma unroll
        for (int j = 0; j < 4; ++j)
            mp[(ty * 4 + i) * 64 + (tx * 4 + j)] = acc[i][j];
}

// qm_relu fused: sums the 4 kv partials, att = relu(q @ M), writes bf16 hi/lo directly
__global__ __launch_bounds__(256)
void qm_relu_split()
{
    int nt = blockIdx.x, h = blockIdx.y, b = blockIdx.z;
    __shared__ float Qs[64][65];
    __shared__ float Ms[64][68];
    int tid = threadIdx.x;
    const float* qbase = g_q + ((size_t)(b * 1024 + nt * 64)) * CDIM + h * 64;
    const float* mbase = g_mpart + (size_t)(b * 8 + h) * 4096;
#pragma unroll
    for (int u = 0; u < 4; ++u) {
        int v = tid + u * 256;
        int r = v >> 4, c4 = v & 15;
        float4 t = *(const float4*)(qbase + (size_t)r * CDIM + c4 * 4);
        Qs[r][c4 * 4 + 0] = t.x; Qs[r][c4 * 4 + 1] = t.y;
        Qs[r][c4 * 4 + 2] = t.z; Qs[r][c4 * 4 + 3] = t.w;
        float4 m0 = *(const float4*)(mbase + r * 64 + c4 * 4);
        float4 m1 = *(const float4*)(mbase + 262144 + r * 64 + c4 * 4);
        float4 m2 = *(const float4*)(mbase + 2 * 262144 + r * 64 + c4 * 4);
        float4 m3 = *(const float4*)(mbase + 3 * 262144 + r * 64 + c4 * 4);
        Ms[r][c4 * 4 + 0] = (m0.x + m1.x + m2.x + m3.x) * SCALE_ATTN;
        Ms[r][c4 * 4 + 1] = (m0.y + m1.y + m2.y + m3.y) * SCALE_ATTN;
        Ms[r][c4 * 4 + 2] = (m0.z + m1.z + m2.z + m3.z) * SCALE_ATTN;
        Ms[r][c4 * 4 + 3] = (m0.w + m1.w + m2.w + m3.w) * SCALE_ATTN;
    }
    __syncthreads();
    int r = tid >> 2, quarter = tid & 3;
    float acc[16];
#pragma unroll
    for (int e = 0; e < 16; ++e) acc[e] = 0.f;
#pragma unroll
    for (int d = 0; d < 64; ++d) {
        float qv = Qs[r][d];
#pragma unroll
        for (int e4 = 0; e4 < 4; ++e4) {
            float4 m = *(const float4*)&Ms[d][quarter * 16 + e4 * 4];
            acc[e4 * 4 + 0] = fmaf(qv, m.x, acc[e4 * 4 + 0]);
            acc[e4 * 4 + 1] = fmaf(qv, m.y, acc[e4 * 4 + 1]);
            acc[e4 * 4 + 2] = fmaf(qv, m.z, acc[e4 * 4 + 2]);
            acc[e4 * 4 + 3] = fmaf(qv, m.w, acc[e4 * 4 + 3]);
        }
    }
    size_t obase = ((size_t)(b * 1024 + nt * 64 + r)) * CDIM + h * 64 + quarter * 16;
#pragma unroll
    for (int e2 = 0; e2 < 8; ++e2) {
        float v0 = fmaxf(acc[e2 * 2 + 0], 0.f);
        float v1 = fmaxf(acc[e2 * 2 + 1], 0.f);
        __nv_bfloat16 h0 = __float2bfloat16(v0);
        __nv_bfloat16 h1 = __float2bfloat16(v1);
        __nv_bfloat162 hh; hh.x = h0; hh.y = h1;
        __nv_bfloat162 ll;
        ll.x = __float2bfloat16(v0 - __bfloat162float(h0));
        ll.y = __float2bfloat16(v1 - __bfloat162float(h1));
        *(__nv_bfloat162*)(g_atth + obase + e2 * 2) = hh;
        *(__nv_bfloat162*)(g_attl + obase + e2 * 2) = ll;
    }
}

// ============================ host launch ============================
extern "C" void kernel_launch(void* const* d_in, const int* in_sizes, int n_in,
                              void* d_out, int out_size)
{
    (void)in_sizes; (void)n_in; (void)out_size;
    const float* x = (const float*)d_in[0];
    const float** p = (const float**)(d_in + 1);   // 24 params: 4 sets x 6

    cudaFuncSetAttribute(gemm_tc, cudaFuncAttributeMaxDynamicSharedMemorySize, GEMM_SMEM);

    fold_split_all<<<4096, 256>>>(
        p[0], p[1], p[2], p[3], p[4], p[5],
        p[6], p[7], p[8], p[9], p[10], p[11],
        p[12], p[13], p[14], p[15], p[16], p[17],
        p[18], p[19], p[20], p[21], p[22], p[23]);

    int n4 = MROWS * CDIM / 4;
    split_bf16_x<<<(n4 + 255) / 256, 256>>>(x, n4);

    dim3 gemmGrid(CDIM / 256, MROWS / 128);   // (2, 64) = 128 CTAs
    gemm_tc<<<gemmGrid, 512, GEMM_SMEM>>>(nullptr, 0, 0, 0);  // q
    gemm_tc<<<gemmGrid, 512, GEMM_SMEM>>>(nullptr, 0, 1, 1);  // k
    gemm_tc<<<gemmGrid, 512, GEMM_SMEM>>>(nullptr, 0, 2, 2);  // v

    kv_outer_partial<<<dim3(64, 4), 256>>>();
    qm_relu_split<<<dim3(16, 8, 8), 256>>>();

    gemm_tc<<<gemmGrid, 512, GEMM_SMEM>>>((float*)d_out, 1, 3, 3);
}

// round 5
// speedup vs baseline: 1.9724x; 1.0374x over previous
#include <cuda_runtime.h>
#include <cuda_bf16.h>
#include <cstdint>

#define EPS_BN 1e-5f
#define SCALE_ATTN 0.125f
#define CDIM 512
#define MROWS 8192   // B*N

// ============================ scratch (static device mem) ============================
__device__ __align__(16) __nv_bfloat16 g_xh[MROWS*CDIM], g_xl[MROWS*CDIM];
__device__ __align__(16) __nv_bfloat16 g_atth[MROWS*CDIM], g_attl[MROWS*CDIM];
__device__ __align__(16) __nv_bfloat16 g_whq[CDIM*CDIM], g_wlq[CDIM*CDIM];
__device__ __align__(16) __nv_bfloat16 g_whk[CDIM*CDIM], g_wlk[CDIM*CDIM];
__device__ __align__(16) __nv_bfloat16 g_whv[CDIM*CDIM], g_wlv[CDIM*CDIM];
__device__ __align__(16) __nv_bfloat16 g_whp[CDIM*CDIM], g_wlp[CDIM*CDIM];
__device__ float g_bq[CDIM], g_bk[CDIM], g_bv[CDIM], g_bp[CDIM];
__device__ __align__(16) float g_q[MROWS*CDIM], g_k[MROWS*CDIM], g_v[MROWS*CDIM];
__device__ float g_mpart[4*64*64*64];

// ============================ portable PTX helpers ============================
__device__ __forceinline__ uint32_t smem_u32(const void* p) {
    uint32_t a;
    asm("{ .reg .u64 t; cvta.to.shared.u64 t, %1; cvt.u32.u64 %0, t; }" : "=r"(a) : "l"(p));
    return a;
}
__device__ __forceinline__ void cp16(uint32_t saddr, const void* g) {
    asm volatile("cp.async.cg.shared.global [%0], [%1], 16;" :: "r"(saddr), "l"(g) : "memory");
}
__device__ __forceinline__ void cp_commit() {
    asm volatile("cp.async.commit_group;" ::: "memory");
}
template <int N> __device__ __forceinline__ void cp_wait() {
    asm volatile("cp.async.wait_group %0;" :: "n"(N) : "memory");
}
__device__ __forceinline__ void ldsm4(uint32_t* r, uint32_t addr) {
    asm volatile("ldmatrix.sync.aligned.m8n8.x4.shared.b16 {%0,%1,%2,%3}, [%4];"
                 : "=r"(r[0]), "=r"(r[1]), "=r"(r[2]), "=r"(r[3]) : "r"(addr));
}
__device__ __forceinline__ void mma_bf16(float* c, const uint32_t* a, uint32_t b0, uint32_t b1) {
    asm volatile(
        "mma.sync.aligned.m16n8k16.row.col.f32.bf16.bf16.f32 "
        "{%0,%1,%2,%3}, {%4,%5,%6,%7}, {%8,%9}, {%0,%1,%2,%3};"
        : "+f"(c[0]), "+f"(c[1]), "+f"(c[2]), "+f"(c[3])
        : "r"(a[0]), "r"(a[1]), "r"(a[2]), "r"(a[3]), "r"(b0), "r"(b1));
}

// ============================ fused BN fold for all 4 weight sets ============================
__global__ void fold_split_all(
    const float* __restrict__ w0, const float* __restrict__ b0, const float* __restrict__ g0,
    const float* __restrict__ be0, const float* __restrict__ mu0, const float* __restrict__ va0,
    const float* __restrict__ w1, const float* __restrict__ b1, const float* __restrict__ g1,
    const float* __restrict__ be1, const float* __restrict__ mu1, const float* __restrict__ va1,
    const float* __restrict__ w2, const float* __restrict__ b2, const float* __restrict__ g2,
    const float* __restrict__ be2, const float* __restrict__ mu2, const float* __restrict__ va2,
    const float* __restrict__ w3, const float* __restrict__ b3, const float* __restrict__ g3,
    const float* __restrict__ be3, const float* __restrict__ mu3, const float* __restrict__ va3)
{
    int gi = blockIdx.x * blockDim.x + threadIdx.x;   // 4 * 262144
    int s = gi >> 18;
    int i = gi & 262143;
    const float *w, *b, *g, *beta, *mu, *var;
    __nv_bfloat16 *wh, *wl;
    float* bias;
    if (s == 0) { w=w0;b=b0;g=g0;beta=be0;mu=mu0;var=va0; wh=g_whq;wl=g_wlq;bias=g_bq; }
    else if (s == 1) { w=w1;b=b1;g=g1;beta=be1;mu=mu1;var=va1; wh=g_whk;wl=g_wlk;bias=g_bk; }
    else if (s == 2) { w=w2;b=b2;g=g2;beta=be2;mu=mu2;var=va2; wh=g_whv;wl=g_wlv;bias=g_bv; }
    else { w=w3;b=b3;g=g3;beta=be3;mu=mu3;var=va3; wh=g_whp;wl=g_wlp;bias=g_bp; }
    int d = i >> 9;
    float sc = g[d] * rsqrtf(var[d] + EPS_BN);
    float wv = w[i] * sc;
    __nv_bfloat16 h = __float2bfloat16(wv);
    wh[i] = h;
    wl[i] = __float2bfloat16(wv - __bfloat162float(h));
    if ((i & 511) == 0) bias[d] = (b[d] - mu[d]) * sc + beta[d];
}

// ============================ fp32 -> bf16 hi/lo split (x only) ============================
__global__ void split_bf16_x(const float* __restrict__ src, int n4)
{
    int i = blockIdx.x * blockDim.x + threadIdx.x;
    if (i >= n4) return;
    float4 v = ((const float4*)src)[i];
    __nv_bfloat16 h0 = __float2bfloat16(v.x), h1 = __float2bfloat16(v.y);
    __nv_bfloat16 h2 = __float2bfloat16(v.z), h3 = __float2bfloat16(v.w);
    __nv_bfloat162 hh0; hh0.x = h0; hh0.y = h1;
    __nv_bfloat162 hh1; hh1.x = h2; hh1.y = h3;
    ((__nv_bfloat162*)g_xh)[i * 2 + 0] = hh0;
    ((__nv_bfloat162*)g_xh)[i * 2 + 1] = hh1;
    __nv_bfloat162 ll0, ll1;
    ll0.x = __float2bfloat16(v.x - __bfloat162float(h0));
    ll0.y = __float2bfloat16(v.y - __bfloat162float(h1));
    ll1.x = __float2bfloat16(v.z - __bfloat162float(h2));
    ll1.y = __float2bfloat16(v.w - __bfloat162float(h3));
    ((__nv_bfloat162*)g_xl)[i * 2 + 0] = ll0;
    ((__nv_bfloat162*)g_xl)[i * 2 + 1] = ll1;
}

// ============================ HMMA GEMM v3: C = relu(A @ W^T + bias) ============================
// CTA tile 128(m) x 256(n), BK=32, 512 threads (16 warps, 64x32 warp tiles), 3-stage cp.async.
// One __syncthreads per stage; term-outer MMA order; A-fragment double-buffering.
#define BK 32
#define NSTAGE (CDIM / BK)          // 16
#define RPITCH 80                   // smem row pitch bytes (64B data + 16B pad)
#define A_TB (128 * RPITCH)         // 10240
#define W_TB (256 * RPITCH)         // 20480
#define STAGEB (2 * A_TB + 2 * W_TB)// 61440: [Ah, Al, Wh, Wl]
#define GEMM_SMEM (3 * STAGEB)      // 184320

__global__ __launch_bounds__(512, 1)
void gemm_tc(float* __restrict__ Cext, int asel, int wsel, int osel)
{
    extern __shared__ char smem[];
    const __nv_bfloat16* Ah = asel ? g_atth : g_xh;
    const __nv_bfloat16* Al = asel ? g_attl : g_xl;
    const __nv_bfloat16* Wh = (wsel == 0) ? g_whq : (wsel == 1) ? g_whk : (wsel == 2) ? g_whv : g_whp;
    const __nv_bfloat16* Wl = (wsel == 0) ? g_wlq : (wsel == 1) ? g_wlk : (wsel == 2) ? g_wlv : g_wlp;
    const float* bias = (wsel == 0) ? g_bq : (wsel == 1) ? g_bk : (wsel == 2) ? g_bv : g_bp;
    float* C = (osel == 0) ? g_q : (osel == 1) ? g_k : (osel == 2) ? g_v : Cext;

    const uint32_t sb = smem_u32(smem);
    const int tid = threadIdx.x;
    const int wid = tid >> 5, lane = tid & 31;
    const int wm = wid & 1, wn = wid >> 1;         // 2(m) x 8(n) warps
    const int bn = blockIdx.x * 256, bm = blockIdx.y * 128;

    const __nv_bfloat16* srcA[2] = { Ah + (size_t)bm * CDIM, Al + (size_t)bm * CDIM };
    const __nv_bfloat16* srcW[2] = { Wh + (size_t)bn * CDIM, Wl + (size_t)bn * CDIM };

    auto load_stage = [&](int s, int buf) {
        uint32_t sbase = sb + buf * STAGEB;
        int kof = s * BK;
#pragma unroll
        for (int t = 0; t < 6; ++t) {
            int idx = tid + t * 512;
            if (idx < 1024) {
                int ten = idx >> 9, v = idx & 511;
                int row = v >> 2, ch = v & 3;
                cp16(sbase + ten * A_TB + row * RPITCH + ch * 16,
                     srcA[ten] + (size_t)row * CDIM + kof + ch * 8);
            } else {
                int j = idx - 1024;
                int ten = j >> 10, v = j & 1023;
                int row = v >> 2, ch = v & 3;
                cp16(sbase + 2 * A_TB + ten * W_TB + row * RPITCH + ch * 16,
                     srcW[ten] + (size_t)row * CDIM + kof + ch * 8);
            }
        }
        cp_commit();
    };

    float acc[4][4][4];
#pragma unroll
    for (int i = 0; i < 4; ++i)
#pragma unroll
        for (int j = 0; j < 4; ++j)
#pragma unroll
            for (int k = 0; k < 4; ++k) acc[i][j][k] = 0.f;

    const int g8 = lane >> 3, l8 = lane & 7;
    const int a_row = (g8 & 1) * 8 + l8;
    const int a_k = (g8 >> 1) * 8;
    const int w_row = (g8 >> 1) * 8 + l8;
    const int w_k = (g8 & 1) * 8;

    // per-lane fixed smem offsets (bytes) for LDSM bases
    const uint32_t aoffL = (wm * 64 + a_row) * RPITCH + a_k * 2;      // + mi*16*RPITCH + kk*2
    const uint32_t woffL = (wn * 32 + w_row) * RPITCH + w_k * 2;      // + j*16*RPITCH + kk*2

    load_stage(0, 0);
    load_stage(1, 1);

    for (int s = 0; s < NSTAGE; ++s) {
        if (s + 1 < NSTAGE) cp_wait<1>(); else cp_wait<0>();
        __syncthreads();
        if (s + 2 < NSTAGE) load_stage(s + 2, (s + 2) % 3);

        const uint32_t base = sb + (s % 3) * STAGEB;
        const uint32_t aB = base + aoffL;
        const uint32_t wB = base + 2 * A_TB + woffL;

#pragma unroll
        for (int kk = 0; kk < BK; kk += 16) {
            uint32_t whf[2][4], wlf[2][4];
#pragma unroll
            for (int j = 0; j < 2; ++j) {
                uint32_t off = wB + j * (16 * RPITCH) + kk * 2;
                ldsm4(whf[j], off);
                ldsm4(wlf[j], off + W_TB);
            }
            uint32_t ahf[2][4], alf[2][4];
            ldsm4(ahf[0], aB + kk * 2);
            ldsm4(alf[0], aB + kk * 2 + A_TB);
#pragma unroll
            for (int mi = 0; mi < 4; ++mi) {
                const int cur = mi & 1;
                if (mi < 3) {
                    uint32_t off = aB + (mi + 1) * (16 * RPITCH) + kk * 2;
                    ldsm4(ahf[cur ^ 1], off);
                    ldsm4(alf[cur ^ 1], off + A_TB);
                }
                // term-outer: 4 independent MMAs between reuses of each accumulator
#pragma unroll
                for (int nj = 0; nj < 4; ++nj)
                    mma_bf16(acc[mi][nj], ahf[cur], whf[nj >> 1][(nj & 1) * 2], whf[nj >> 1][(nj & 1) * 2 + 1]);
#pragma unroll
                for (int nj = 0; nj < 4; ++nj)
                    mma_bf16(acc[mi][nj], ahf[cur], wlf[nj >> 1][(nj & 1) * 2], wlf[nj >> 1][(nj & 1) * 2 + 1]);
#pragma unroll
                for (int nj = 0; nj < 4; ++nj)
                    mma_bf16(acc[mi][nj], alf[cur], whf[nj >> 1][(nj & 1) * 2], whf[nj >> 1][(nj & 1) * 2 + 1]);
            }
        }
    }

    const int r_in = lane >> 2;
    const int c_in = (lane & 3) * 2;
#pragma unroll
    for (int mi = 0; mi < 4; ++mi) {
        int r0 = bm + wm * 64 + mi * 16 + r_in;
#pragma unroll
        for (int nj = 0; nj < 4; ++nj) {
            int c0 = bn + wn * 32 + nj * 8 + c_in;
            float b0 = bias[c0], b1 = bias[c0 + 1];
            float2 lo, hi;
            lo.x = fmaxf(acc[mi][nj][0] + b0, 0.f);
            lo.y = fmaxf(acc[mi][nj][1] + b1, 0.f);
            hi.x = fmaxf(acc[mi][nj][2] + b0, 0.f);
            hi.y = fmaxf(acc[mi][nj][3] + b1, 0.f);
            *(float2*)(C + (size_t)r0 * CDIM + c0) = lo;
            *(float2*)(C + (size_t)(r0 + 8) * CDIM + c0) = hi;
        }
    }
}

// ============================ attention middle ============================
__global__ __launch_bounds__(256)
void kv_outer_partial()
{
    int bh = blockIdx.x, part = blockIdx.y;
    int b = bh >> 3, h = bh & 7;
    __shared__ float Ks[32][64];
    __shared__ float Vs[32][64];
    int tid = threadIdx.x;
    int tx = tid & 15, ty = tid >> 4;
    const float* kbase = g_k + ((size_t)b * 1024) * CDIM + h * 64;
    const float* vbase = g_v + ((size_t)b * 1024) * CDIM + h * 64;
    float acc[4][4];
#pragma unroll
    for (int i = 0; i < 4; ++i)
#pragma unroll
        for (int j = 0; j < 4; ++j) acc[i][j] = 0.f;
    int nbeg = part * 256, nend = nbeg + 256;
    for (int n0 = nbeg; n0 < nend; n0 += 32) {
#pragma unroll
        for (int u = 0; u < 2; ++u) {
            int v = tid + u * 256;
            int r = v >> 4, c4 = v & 15;
            *(float4*)&Ks[r][c4 * 4] = *(const float4*)(kbase + (size_t)(n0 + r) * CDIM + c4 * 4);
            *(float4*)&Vs[r][c4 * 4] = *(const float4*)(vbase + (size_t)(n0 + r) * CDIM + c4 * 4);
        }
        __syncthreads();
#pragma unroll
        for (int nn = 0; nn < 32; ++nn) {
            float4 kv = *(const float4*)&Ks[nn][ty * 4];
            float4 vv = *(const float4*)&Vs[nn][tx * 4];
            float ka[4] = {kv.x, kv.y, kv.z, kv.w};
            float va[4] = {vv.x, vv.y, vv.z, vv.w};
#pragma unroll
            for (int i = 0; i < 4; ++i)
#pragma unroll
                for (int j = 0; j < 4; ++j)
                    acc[i][j] = fmaf(ka[i], va[j], acc[i][j]);
        }
        __syncthreads();
    }
    float* mp = g_mpart + ((size_t)part * 64 + bh) * 4096;
#pragma unroll
    for (int i = 0; i < 4; ++i)
#pragma unroll
        for (int j = 0; j < 4; ++j)
            mp[(ty * 4 + i) * 64 + (tx * 4 + j)] = acc[i][j];
}

// qm_relu fused: sums the 4 kv partials, att = relu(q @ M), writes bf16 hi/lo directly
__global__ __launch_bounds__(256)
void qm_relu_split()
{
    int nt = blockIdx.x, h = blockIdx.y, b = blockIdx.z;
    __shared__ float Qs[64][65];
    __shared__ float Ms[64][68];
    int tid = threadIdx.x;
    const float* qbase = g_q + ((size_t)(b * 1024 + nt * 64)) * CDIM + h * 64;
    const float* mbase = g_mpart + (size_t)(b * 8 + h) * 4096;
#pragma unroll
    for (int u = 0; u < 4; ++u) {
        int v = tid + u * 256;
        int r = v >> 4, c4 = v & 15;
        float4 t = *(const float4*)(qbase + (size_t)r * CDIM + c4 * 4);
        Qs[r][c4 * 4 + 0] = t.x; Qs[r][c4 * 4 + 1] = t.y;
        Qs[r][c4 * 4 + 2] = t.z; Qs[r][c4 * 4 + 3] = t.w;
        float4 m0 = *(const float4*)(mbase + r * 64 + c4 * 4);
        float4 m1 = *(const float4*)(mbase + 262144 + r * 64 + c4 * 4);
        float4 m2 = *(const float4*)(mbase + 2 * 262144 + r * 64 + c4 * 4);
        float4 m3 = *(const float4*)(mbase + 3 * 262144 + r * 64 + c4 * 4);
        Ms[r][c4 * 4 + 0] = (m0.x + m1.x + m2.x + m3.x) * SCALE_ATTN;
        Ms[r][c4 * 4 + 1] = (m0.y + m1.y + m2.y + m3.y) * SCALE_ATTN;
        Ms[r][c4 * 4 + 2] = (m0.z + m1.z + m2.z + m3.z) * SCALE_ATTN;
        Ms[r][c4 * 4 + 3] = (m0.w + m1.w + m2.w + m3.w) * SCALE_ATTN;
    }
    __syncthreads();
    int r = tid >> 2, quarter = tid & 3;
    float acc[16];
#pragma unroll
    for (int e = 0; e < 16; ++e) acc[e] = 0.f;
#pragma unroll
    for (int d = 0; d < 64; ++d) {
        float qv = Qs[r][d];
#pragma unroll
        for (int e4 = 0; e4 < 4; ++e4) {
            float4 m = *(const float4*)&Ms[d][quarter * 16 + e4 * 4];
            acc[e4 * 4 + 0] = fmaf(qv, m.x, acc[e4 * 4 + 0]);
            acc[e4 * 4 + 1] = fmaf(qv, m.y, acc[e4 * 4 + 1]);
            acc[e4 * 4 + 2] = fmaf(qv, m.z, acc[e4 * 4 + 2]);
            acc[e4 * 4 + 3] = fmaf(qv, m.w, acc[e4 * 4 + 3]);
        }
    }
    size_t obase = ((size_t)(b * 1024 + nt * 64 + r)) * CDIM + h * 64 + quarter * 16;
#pragma unroll
    for (int e2 = 0; e2 < 8; ++e2) {
        float v0 = fmaxf(acc[e2 * 2 + 0], 0.f);
        float v1 = fmaxf(acc[e2 * 2 + 1], 0.f);
        __nv_bfloat16 h0 = __float2bfloat16(v0);
        __nv_bfloat16 h1 = __float2bfloat16(v1);
        __nv_bfloat162 hh; hh.x = h0; hh.y = h1;
        __nv_bfloat162 ll;
        ll.x = __float2bfloat16(v0 - __bfloat162float(h0));
        ll.y = __float2bfloat16(v1 - __bfloat162float(h1));
        *(__nv_bfloat162*)(g_atth + obase + e2 * 2) = hh;
        *(__nv_bfloat162*)(g_attl + obase + e2 * 2) = ll;
    }
}

// ============================ host launch ============================
extern "C" void kernel_launch(void* const* d_in, const int* in_sizes, int n_in,
                              void* d_out, int out_size)
{
    (void)in_sizes; (void)n_in; (void)out_size;
    const float* x = (const float*)d_in[0];
    const float** p = (const float**)(d_in + 1);   // 24 params: 4 sets x 6

    cudaFuncSetAttribute(gemm_tc, cudaFuncAttributeMaxDynamicSharedMemorySize, GEMM_SMEM);

    fold_split_all<<<4096, 256>>>(
        p[0], p[1], p[2], p[3], p[4], p[5],
        p[6], p[7], p[8], p[9], p[10], p[11],
        p[12], p[13], p[14], p[15], p[16], p[17],
        p[18], p[19], p[20], p[21], p[22], p[23]);

    int n4 = MROWS * CDIM / 4;
    split_bf16_x<<<(n4 + 255) / 256, 256>>>(x, n4);

    dim3 gemmGrid(CDIM / 256, MROWS / 128);   // (2, 64) = 128 CTAs
    gemm_tc<<<gemmGrid, 512, GEMM_SMEM>>>(nullptr, 0, 0, 0);  // q
    gemm_tc<<<gemmGrid, 512, GEMM_SMEM>>>(nullptr, 0, 1, 1);  // k
    gemm_tc<<<gemmGrid, 512, GEMM_SMEM>>>(nullptr, 0, 2, 2);  // v

    kv_outer_partial<<<dim3(64, 4), 256>>>();
    qm_relu_split<<<dim3(16, 8, 8), 256>>>();

    gemm_tc<<<gemmGrid, 512, GEMM_SMEM>>>((float*)d_out, 1, 3, 3);
}

// round 6
// speedup vs baseline: 2.0359x; 1.0322x over previous
#include <cuda_runtime.h>
#include <cuda_bf16.h>
#include <cstdint>

#define EPS_BN 1e-5f
#define SCALE_ATTN 0.125f
#define CDIM 512
#define MROWS 8192   // B*N

// ============================ scratch (static device mem) ============================
__device__ __align__(16) __nv_bfloat16 g_xh[MROWS*CDIM], g_xl[MROWS*CDIM];
__device__ __align__(16) __nv_bfloat16 g_atth[MROWS*CDIM], g_attl[MROWS*CDIM];
__device__ __align__(16) __nv_bfloat16 g_whq[CDIM*CDIM], g_wlq[CDIM*CDIM];
__device__ __align__(16) __nv_bfloat16 g_whk[CDIM*CDIM], g_wlk[CDIM*CDIM];
__device__ __align__(16) __nv_bfloat16 g_whv[CDIM*CDIM], g_wlv[CDIM*CDIM];
__device__ __align__(16) __nv_bfloat16 g_whp[CDIM*CDIM], g_wlp[CDIM*CDIM];
__device__ float g_bq[CDIM], g_bk[CDIM], g_bv[CDIM], g_bp[CDIM];
__device__ __align__(16) float g_q[MROWS*CDIM], g_k[MROWS*CDIM], g_v[MROWS*CDIM];
__device__ float g_mpart[4*64*64*64];

// ============================ portable PTX helpers ============================
__device__ __forceinline__ uint32_t smem_u32(const void* p) {
    uint32_t a;
    asm("{ .reg .u64 t; cvta.to.shared.u64 t, %1; cvt.u32.u64 %0, t; }" : "=r"(a) : "l"(p));
    return a;
}
__device__ __forceinline__ void cp16(uint32_t saddr, const void* g) {
    asm volatile("cp.async.cg.shared.global [%0], [%1], 16;" :: "r"(saddr), "l"(g) : "memory");
}
__device__ __forceinline__ void cp_commit() {
    asm volatile("cp.async.commit_group;" ::: "memory");
}
template <int N> __device__ __forceinline__ void cp_wait() {
    asm volatile("cp.async.wait_group %0;" :: "n"(N) : "memory");
}
__device__ __forceinline__ void ldsm4(uint32_t* r, uint32_t addr) {
    asm volatile("ldmatrix.sync.aligned.m8n8.x4.shared.b16 {%0,%1,%2,%3}, [%4];"
                 : "=r"(r[0]), "=r"(r[1]), "=r"(r[2]), "=r"(r[3]) : "r"(addr));
}
__device__ __forceinline__ void mma_bf16(float* c, const uint32_t* a, uint32_t b0, uint32_t b1) {
    asm volatile(
        "mma.sync.aligned.m16n8k16.row.col.f32.bf16.bf16.f32 "
        "{%0,%1,%2,%3}, {%4,%5,%6,%7}, {%8,%9}, {%0,%1,%2,%3};"
        : "+f"(c[0]), "+f"(c[1]), "+f"(c[2]), "+f"(c[3])
        : "r"(a[0]), "r"(a[1]), "r"(a[2]), "r"(a[3]), "r"(b0), "r"(b1));
}

// ============================ fused BN fold for all 4 weight sets ============================
__global__ void fold_split_all(
    const float* __restrict__ w0, const float* __restrict__ b0, const float* __restrict__ g0,
    const float* __restrict__ be0, const float* __restrict__ mu0, const float* __restrict__ va0,
    const float* __restrict__ w1, const float* __restrict__ b1, const float* __restrict__ g1,
    const float* __restrict__ be1, const float* __restrict__ mu1, const float* __restrict__ va1,
    const float* __restrict__ w2, const float* __restrict__ b2, const float* __restrict__ g2,
    const float* __restrict__ be2, const float* __restrict__ mu2, const float* __restrict__ va2,
    const float* __restrict__ w3, const float* __restrict__ b3, const float* __restrict__ g3,
    const float* __restrict__ be3, const float* __restrict__ mu3, const float* __restrict__ va3)
{
    int gi = blockIdx.x * blockDim.x + threadIdx.x;   // 4 * 262144
    int s = gi >> 18;
    int i = gi & 262143;
    const float *w, *b, *g, *beta, *mu, *var;
    __nv_bfloat16 *wh, *wl;
    float* bias;
    if (s == 0) { w=w0;b=b0;g=g0;beta=be0;mu=mu0;var=va0; wh=g_whq;wl=g_wlq;bias=g_bq; }
    else if (s == 1) { w=w1;b=b1;g=g1;beta=be1;mu=mu1;var=va1; wh=g_whk;wl=g_wlk;bias=g_bk; }
    else if (s == 2) { w=w2;b=b2;g=g2;beta=be2;mu=mu2;var=va2; wh=g_whv;wl=g_wlv;bias=g_bv; }
    else { w=w3;b=b3;g=g3;beta=be3;mu=mu3;var=va3; wh=g_whp;wl=g_wlp;bias=g_bp; }
    int d = i >> 9;
    float sc = g[d] * rsqrtf(var[d] + EPS_BN);
    float wv = w[i] * sc;
    __nv_bfloat16 h = __float2bfloat16(wv);
    wh[i] = h;
    wl[i] = __float2bfloat16(wv - __bfloat162float(h));
    if ((i & 511) == 0) bias[d] = (b[d] - mu[d]) * sc + beta[d];
}

// ============================ fp32 -> bf16 hi/lo split (x only) ============================
__global__ void split_bf16_x(const float* __restrict__ src, int n4)
{
    int i = blockIdx.x * blockDim.x + threadIdx.x;
    if (i >= n4) return;
    float4 v = ((const float4*)src)[i];
    __nv_bfloat16 h0 = __float2bfloat16(v.x), h1 = __float2bfloat16(v.y);
    __nv_bfloat16 h2 = __float2bfloat16(v.z), h3 = __float2bfloat16(v.w);
    __nv_bfloat162 hh0; hh0.x = h0; hh0.y = h1;
    __nv_bfloat162 hh1; hh1.x = h2; hh1.y = h3;
    ((__nv_bfloat162*)g_xh)[i * 2 + 0] = hh0;
    ((__nv_bfloat162*)g_xh)[i * 2 + 1] = hh1;
    __nv_bfloat162 ll0, ll1;
    ll0.x = __float2bfloat16(v.x - __bfloat162float(h0));
    ll0.y = __float2bfloat16(v.y - __bfloat162float(h1));
    ll1.x = __float2bfloat16(v.z - __bfloat162float(h2));
    ll1.y = __float2bfloat16(v.w - __bfloat162float(h3));
    ((__nv_bfloat162*)g_xl)[i * 2 + 0] = ll0;
    ((__nv_bfloat162*)g_xl)[i * 2 + 1] = ll1;
}

// ============================ HMMA GEMM v4: C = relu(A @ W^T + bias) ============================
// 128x128 CTA tile, BK=32, 256 threads (8 warps, 64x32 warp tiles), 2-stage cp.async,
// 2 CTAs/SM. mode 0: fused QKV from x (grid 12 x 64); mode 1: P from att (grid 4 x 64).
#define BK 32
#define NSTAGE (CDIM / BK)          // 16
#define RPITCH 80                   // smem row pitch bytes (64B data + 16B pad)
#define T_TB (128 * RPITCH)         // 10240 per operand tile
#define STAGEB (4 * T_TB)           // 40960: [Ah, Al, Wh, Wl]
#define GEMM_SMEM (2 * STAGEB)      // 81920

__global__ __launch_bounds__(256, 2)
void gemm_tc(float* __restrict__ Cext, int mode)
{
    extern __shared__ char smem[];
    const __nv_bfloat16 *Ah, *Al, *Wh, *Wl;
    const float* bias;
    float* C;
    int bn;
    if (mode == 0) {
        int sel = blockIdx.x >> 2;          // 0=q, 1=k, 2=v
        bn = (blockIdx.x & 3) * 128;
        Ah = g_xh; Al = g_xl;
        Wh = (sel == 0) ? g_whq : (sel == 1) ? g_whk : g_whv;
        Wl = (sel == 0) ? g_wlq : (sel == 1) ? g_wlk : g_wlv;
        bias = (sel == 0) ? g_bq : (sel == 1) ? g_bk : g_bv;
        C = (sel == 0) ? g_q : (sel == 1) ? g_k : g_v;
    } else {
        bn = blockIdx.x * 128;
        Ah = g_atth; Al = g_attl;
        Wh = g_whp; Wl = g_wlp; bias = g_bp;
        C = Cext;
    }
    const int bm = blockIdx.y * 128;

    const uint32_t sb = smem_u32(smem);
    const int tid = threadIdx.x;
    const int wid = tid >> 5, lane = tid & 31;
    const int wm = wid & 1, wn = wid >> 1;   // 2(m) x 4(n)

    const __nv_bfloat16* srcA[2] = { Ah + (size_t)bm * CDIM, Al + (size_t)bm * CDIM };
    const __nv_bfloat16* srcW[2] = { Wh + (size_t)bn * CDIM, Wl + (size_t)bn * CDIM };

    // 2048 16B-chunks per stage (4 tensors x 128 rows x 4 chunks), 8 per thread
    auto load_stage = [&](int s, int buf) {
        uint32_t sbase = sb + buf * STAGEB;
        int kof = s * BK;
#pragma unroll
        for (int t = 0; t < 8; ++t) {
            int idx = tid + t * 256;
            int ten = idx >> 9;              // 0=Ah 1=Al 2=Wh 3=Wl
            int v = idx & 511;
            int row = v >> 2, ch = v & 3;
            const __nv_bfloat16* g =
                (ten < 2 ? srcA[ten] : srcW[ten - 2]) + (size_t)row * CDIM + kof + ch * 8;
            cp16(sbase + ten * T_TB + row * RPITCH + ch * 16, g);
        }
        cp_commit();
    };

    float acc[4][4][4];
#pragma unroll
    for (int i = 0; i < 4; ++i)
#pragma unroll
        for (int j = 0; j < 4; ++j)
#pragma unroll
            for (int k = 0; k < 4; ++k) acc[i][j][k] = 0.f;

    const int g8 = lane >> 3, l8 = lane & 7;
    const int a_row = (g8 & 1) * 8 + l8;
    const int a_k = (g8 >> 1) * 8;
    const int w_row = (g8 >> 1) * 8 + l8;
    const int w_k = (g8 & 1) * 8;

    const uint32_t aoffL = (wm * 64 + a_row) * RPITCH + a_k * 2;
    const uint32_t woffL = (wn * 32 + w_row) * RPITCH + w_k * 2;

    load_stage(0, 0);

    for (int s = 0; s < NSTAGE; ++s) {
        cp_wait<0>();
        __syncthreads();                         // all warps done with buf (s+1)&1 from stage s-1
        if (s + 1 < NSTAGE) load_stage(s + 1, (s + 1) & 1);

        const uint32_t base = sb + (s & 1) * STAGEB;
        const uint32_t aB = base + aoffL;
        const uint32_t wB = base + 2 * T_TB + woffL;

#pragma unroll
        for (int kk = 0; kk < BK; kk += 16) {
            uint32_t whf[2][4], wlf[2][4];
#pragma unroll
            for (int j = 0; j < 2; ++j) {
                uint32_t off = wB + j * (16 * RPITCH) + kk * 2;
                ldsm4(whf[j], off);
                ldsm4(wlf[j], off + T_TB);
            }
            uint32_t ahf[2][4], alf[2][4];
            ldsm4(ahf[0], aB + kk * 2);
            ldsm4(alf[0], aB + kk * 2 + T_TB);
#pragma unroll
            for (int mi = 0; mi < 4; ++mi) {
                const int cur = mi & 1;
                if (mi < 3) {
                    uint32_t off = aB + (mi + 1) * (16 * RPITCH) + kk * 2;
                    ldsm4(ahf[cur ^ 1], off);
                    ldsm4(alf[cur ^ 1], off + T_TB);
                }
#pragma unroll
                for (int nj = 0; nj < 4; ++nj)
                    mma_bf16(acc[mi][nj], ahf[cur], whf[nj >> 1][(nj & 1) * 2], whf[nj >> 1][(nj & 1) * 2 + 1]);
#pragma unroll
                for (int nj = 0; nj < 4; ++nj)
                    mma_bf16(acc[mi][nj], ahf[cur], wlf[nj >> 1][(nj & 1) * 2], wlf[nj >> 1][(nj & 1) * 2 + 1]);
#pragma unroll
                for (int nj = 0; nj < 4; ++nj)
                    mma_bf16(acc[mi][nj], alf[cur], whf[nj >> 1][(nj & 1) * 2], whf[nj >> 1][(nj & 1) * 2 + 1]);
            }
        }
    }

    const int r_in = lane >> 2;
    const int c_in = (lane & 3) * 2;
#pragma unroll
    for (int mi = 0; mi < 4; ++mi) {
        int r0 = bm + wm * 64 + mi * 16 + r_in;
#pragma unroll
        for (int nj = 0; nj < 4; ++nj) {
            int c0 = bn + wn * 32 + nj * 8 + c_in;
            float b0 = bias[c0], b1 = bias[c0 + 1];
            float2 lo, hi;
            lo.x = fmaxf(acc[mi][nj][0] + b0, 0.f);
            lo.y = fmaxf(acc[mi][nj][1] + b1, 0.f);
            hi.x = fmaxf(acc[mi][nj][2] + b0, 0.f);
            hi.y = fmaxf(acc[mi][nj][3] + b1, 0.f);
            *(float2*)(C + (size_t)r0 * CDIM + c0) = lo;
            *(float2*)(C + (size_t)(r0 + 8) * CDIM + c0) = hi;
        }
    }
}

// ============================ attention middle ============================
__global__ __launch_bounds__(256)
void kv_outer_partial()
{
    int bh = blockIdx.x, part = blockIdx.y;
    int b = bh >> 3, h = bh & 7;
    __shared__ float Ks[32][64];
    __shared__ float Vs[32][64];
    int tid = threadIdx.x;
    int tx = tid & 15, ty = tid >> 4;
    const float* kbase = g_k + ((size_t)b * 1024) * CDIM + h * 64;
    const float* vbase = g_v + ((size_t)b * 1024) * CDIM + h * 64;
    float acc[4][4];
#pragma unroll
    for (int i = 0; i < 4; ++i)
#pragma unroll
        for (int j = 0; j < 4; ++j) acc[i][j] = 0.f;
    int nbeg = part * 256, nend = nbeg + 256;
    for (int n0 = nbeg; n0 < nend; n0 += 32) {
#pragma unroll
        for (int u = 0; u < 2; ++u) {
            int v = tid + u * 256;
            int r = v >> 4, c4 = v & 15;
            *(float4*)&Ks[r][c4 * 4] = *(const float4*)(kbase + (size_t)(n0 + r) * CDIM + c4 * 4);
            *(float4*)&Vs[r][c4 * 4] = *(const float4*)(vbase + (size_t)(n0 + r) * CDIM + c4 * 4);
        }
        __syncthreads();
#pragma unroll
        for (int nn = 0; nn < 32; ++nn) {
            float4 kv = *(const float4*)&Ks[nn][ty * 4];
            float4 vv = *(const float4*)&Vs[nn][tx * 4];
            float ka[4] = {kv.x, kv.y, kv.z, kv.w};
            float va[4] = {vv.x, vv.y, vv.z, vv.w};
#pragma unroll
            for (int i = 0; i < 4; ++i)
#pragma unroll
                for (int j = 0; j < 4; ++j)
                    acc[i][j] = fmaf(ka[i], va[j], acc[i][j]);
        }
        __syncthreads();
    }
    float* mp = g_mpart + ((size_t)part * 64 + bh) * 4096;
#pragma unroll
    for (int i = 0; i < 4; ++i)
#pragma unroll
        for (int j = 0; j < 4; ++j)
            mp[(ty * 4 + i) * 64 + (tx * 4 + j)] = acc[i][j];
}

// qm_relu fused: sums the 4 kv partials, att = relu(q @ M), writes bf16 hi/lo directly
__global__ __launch_bounds__(256)
void qm_relu_split()
{
    int nt = blockIdx.x, h = blockIdx.y, b = blockIdx.z;
    __shared__ float Qs[64][65];
    __shared__ float Ms[64][68];
    int tid = threadIdx.x;
    const float* qbase = g_q + ((size_t)(b * 1024 + nt * 64)) * CDIM + h * 64;
    const float* mbase = g_mpart + (size_t)(b * 8 + h) * 4096;
#pragma unroll
    for (int u = 0; u < 4; ++u) {
        int v = tid + u * 256;
        int r = v >> 4, c4 = v & 15;
        float4 t = *(const float4*)(qbase + (size_t)r * CDIM + c4 * 4);
        Qs[r][c4 * 4 + 0] = t.x; Qs[r][c4 * 4 + 1] = t.y;
        Qs[r][c4 * 4 + 2] = t.z; Qs[r][c4 * 4 + 3] = t.w;
        float4 m0 = *(const float4*)(mbase + r * 64 + c4 * 4);
        float4 m1 = *(const float4*)(mbase + 262144 + r * 64 + c4 * 4);
        float4 m2 = *(const float4*)(mbase + 2 * 262144 + r * 64 + c4 * 4);
        float4 m3 = *(const float4*)(mbase + 3 * 262144 + r * 64 + c4 * 4);
        Ms[r][c4 * 4 + 0] = (m0.x + m1.x + m2.x + m3.x) * SCALE_ATTN;
        Ms[r][c4 * 4 + 1] = (m0.y + m1.y + m2.y + m3.y) * SCALE_ATTN;
        Ms[r][c4 * 4 + 2] = (m0.z + m1.z + m2.z + m3.z) * SCALE_ATTN;
        Ms[r][c4 * 4 + 3] = (m0.w + m1.w + m2.w + m3.w) * SCALE_ATTN;
    }
    __syncthreads();
    int r = tid >> 2, quarter = tid & 3;
    float acc[16];
#pragma unroll
    for (int e = 0; e < 16; ++e) acc[e] = 0.f;
#pragma unroll
    for (int d = 0; d < 64; ++d) {
        float qv = Qs[r][d];
#pragma unroll
        for (int e4 = 0; e4 < 4; ++e4) {
            float4 m = *(const float4*)&Ms[d][quarter * 16 + e4 * 4];
            acc[e4 * 4 + 0] = fmaf(qv, m.x, acc[e4 * 4 + 0]);
            acc[e4 * 4 + 1] = fmaf(qv, m.y, acc[e4 * 4 + 1]);
            acc[e4 * 4 + 2] = fmaf(qv, m.z, acc[e4 * 4 + 2]);
            acc[e4 * 4 + 3] = fmaf(qv, m.w, acc[e4 * 4 + 3]);
        }
    }
    size_t obase = ((size_t)(b * 1024 + nt * 64 + r)) * CDIM + h * 64 + quarter * 16;
#pragma unroll
    for (int e2 = 0; e2 < 8; ++e2) {
        float v0 = fmaxf(acc[e2 * 2 + 0], 0.f);
        float v1 = fmaxf(acc[e2 * 2 + 1], 0.f);
        __nv_bfloat16 h0 = __float2bfloat16(v0);
        __nv_bfloat16 h1 = __float2bfloat16(v1);
        __nv_bfloat162 hh; hh.x = h0; hh.y = h1;
        __nv_bfloat162 ll;
        ll.x = __float2bfloat16(v0 - __bfloat162float(h0));
        ll.y = __float2bfloat16(v1 - __bfloat162float(h1));
        *(__nv_bfloat162*)(g_atth + obase + e2 * 2) = hh;
        *(__nv_bfloat162*)(g_attl + obase + e2 * 2) = ll;
    }
}

// ============================ host launch ============================
extern "C" void kernel_launch(void* const* d_in, const int* in_sizes, int n_in,
                              void* d_out, int out_size)
{
    (void)in_sizes; (void)n_in; (void)out_size;
    const float* x = (const float*)d_in[0];
    const float** p = (const float**)(d_in + 1);   // 24 params: 4 sets x 6

    cudaFuncSetAttribute(gemm_tc, cudaFuncAttributeMaxDynamicSharedMemorySize, GEMM_SMEM);

    fold_split_all<<<4096, 256>>>(
        p[0], p[1], p[2], p[3], p[4], p[5],
        p[6], p[7], p[8], p[9], p[10], p[11],
        p[12], p[13], p[14], p[15], p[16], p[17],
        p[18], p[19], p[20], p[21], p[22], p[23]);

    int n4 = MROWS * CDIM / 4;
    split_bf16_x<<<(n4 + 255) / 256, 256>>>(x, n4);

    // fused QKV: grid (12, 64) = 768 CTAs, 2 CTAs/SM
    gemm_tc<<<dim3(12, 64), 256, GEMM_SMEM>>>(nullptr, 0);

    kv_outer_partial<<<dim3(64, 4), 256>>>();
    qm_relu_split<<<dim3(16, 8, 8), 256>>>();

    // P projection
    gemm_tc<<<dim3(4, 64), 256, GEMM_SMEM>>>((float*)d_out, 1);
}

// round 7
// speedup vs baseline: 2.0697x; 1.0166x over previous
#include <cuda_runtime.h>
#include <cuda_bf16.h>
#include <cstdint>

#define EPS_BN 1e-5f
#define SCALE_ATTN 0.125f
#define CDIM 512
#define MROWS 8192   // B*N

// ============================ scratch (static device mem) ============================
__device__ __align__(16) __nv_bfloat16 g_xh[MROWS*CDIM], g_xl[MROWS*CDIM];
__device__ __align__(16) __nv_bfloat16 g_atth[MROWS*CDIM], g_attl[MROWS*CDIM];
__device__ __align__(16) __nv_bfloat16 g_whq[CDIM*CDIM], g_wlq[CDIM*CDIM];
__device__ __align__(16) __nv_bfloat16 g_whk[CDIM*CDIM], g_wlk[CDIM*CDIM];
__device__ __align__(16) __nv_bfloat16 g_whv[CDIM*CDIM], g_wlv[CDIM*CDIM];
__device__ __align__(16) __nv_bfloat16 g_whp[CDIM*CDIM], g_wlp[CDIM*CDIM];
__device__ float g_bq[CDIM], g_bk[CDIM], g_bv[CDIM], g_bp[CDIM];
__device__ __align__(16) float g_q[MROWS*CDIM], g_k[MROWS*CDIM], g_v[MROWS*CDIM];
__device__ __align__(16) float g_m[64*64*64];
__device__ __align__(16) float g_mpart[8*64*64*64];   // 8 partials

// ============================ portable PTX helpers ============================
__device__ __forceinline__ uint32_t smem_u32(const void* p) {
    uint32_t a;
    asm("{ .reg .u64 t; cvta.to.shared.u64 t, %1; cvt.u32.u64 %0, t; }" : "=r"(a) : "l"(p));
    return a;
}
__device__ __forceinline__ void cp16(uint32_t saddr, const void* g) {
    asm volatile("cp.async.cg.shared.global [%0], [%1], 16;" :: "r"(saddr), "l"(g) : "memory");
}
__device__ __forceinline__ void cp_commit() {
    asm volatile("cp.async.commit_group;" ::: "memory");
}
template <int N> __device__ __forceinline__ void cp_wait() {
    asm volatile("cp.async.wait_group %0;" :: "n"(N) : "memory");
}
__device__ __forceinline__ void ldsm4(uint32_t* r, uint32_t addr) {
    asm volatile("ldmatrix.sync.aligned.m8n8.x4.shared.b16 {%0,%1,%2,%3}, [%4];"
                 : "=r"(r[0]), "=r"(r[1]), "=r"(r[2]), "=r"(r[3]) : "r"(addr));
}
__device__ __forceinline__ void mma_bf16(float* c, const uint32_t* a, uint32_t b0, uint32_t b1) {
    asm volatile(
        "mma.sync.aligned.m16n8k16.row.col.f32.bf16.bf16.f32 "
        "{%0,%1,%2,%3}, {%4,%5,%6,%7}, {%8,%9}, {%0,%1,%2,%3};"
        : "+f"(c[0]), "+f"(c[1]), "+f"(c[2]), "+f"(c[3])
        : "r"(a[0]), "r"(a[1]), "r"(a[2]), "r"(a[3]), "r"(b0), "r"(b1));
}

// ============================ fused prep: BN-fold all 4 sets + split x ============================
// blocks [0, 4096): fold 4x262144 weight elems. blocks [4096, 8192): split x (1M float4).
__global__ void prep_all(
    const float* __restrict__ x,
    const float* __restrict__ w0, const float* __restrict__ b0, const float* __restrict__ g0,
    const float* __restrict__ be0, const float* __restrict__ mu0, const float* __restrict__ va0,
    const float* __restrict__ w1, const float* __restrict__ b1, const float* __restrict__ g1,
    const float* __restrict__ be1, const float* __restrict__ mu1, const float* __restrict__ va1,
    const float* __restrict__ w2, const float* __restrict__ b2, const float* __restrict__ g2,
    const float* __restrict__ be2, const float* __restrict__ mu2, const float* __restrict__ va2,
    const float* __restrict__ w3, const float* __restrict__ b3, const float* __restrict__ g3,
    const float* __restrict__ be3, const float* __restrict__ mu3, const float* __restrict__ va3)
{
    if (blockIdx.x < 4096) {
        int gi = blockIdx.x * 256 + threadIdx.x;   // 4 * 262144
        int s = gi >> 18;
        int i = gi & 262143;
        const float *w, *b, *g, *beta, *mu, *var;
        __nv_bfloat16 *wh, *wl;
        float* bias;
        if (s == 0) { w=w0;b=b0;g=g0;beta=be0;mu=mu0;var=va0; wh=g_whq;wl=g_wlq;bias=g_bq; }
        else if (s == 1) { w=w1;b=b1;g=g1;beta=be1;mu=mu1;var=va1; wh=g_whk;wl=g_wlk;bias=g_bk; }
        else if (s == 2) { w=w2;b=b2;g=g2;beta=be2;mu=mu2;var=va2; wh=g_whv;wl=g_wlv;bias=g_bv; }
        else { w=w3;b=b3;g=g3;beta=be3;mu=mu3;var=va3; wh=g_whp;wl=g_wlp;bias=g_bp; }
        int d = i >> 9;
        float sc = g[d] * rsqrtf(var[d] + EPS_BN);
        float wv = w[i] * sc;
        __nv_bfloat16 h = __float2bfloat16(wv);
        wh[i] = h;
        wl[i] = __float2bfloat16(wv - __bfloat162float(h));
        if ((i & 511) == 0) bias[d] = (b[d] - mu[d]) * sc + beta[d];
    } else {
        int i = (blockIdx.x - 4096) * 256 + threadIdx.x;   // over 1M float4
        float4 v = ((const float4*)x)[i];
        __nv_bfloat16 h0 = __float2bfloat16(v.x), h1 = __float2bfloat16(v.y);
        __nv_bfloat16 h2 = __float2bfloat16(v.z), h3 = __float2bfloat16(v.w);
        __nv_bfloat162 hh0; hh0.x = h0; hh0.y = h1;
        __nv_bfloat162 hh1; hh1.x = h2; hh1.y = h3;
        ((__nv_bfloat162*)g_xh)[i * 2 + 0] = hh0;
        ((__nv_bfloat162*)g_xh)[i * 2 + 1] = hh1;
        __nv_bfloat162 ll0, ll1;
        ll0.x = __float2bfloat16(v.x - __bfloat162float(h0));
        ll0.y = __float2bfloat16(v.y - __bfloat162float(h1));
        ll1.x = __float2bfloat16(v.z - __bfloat162float(h2));
        ll1.y = __float2bfloat16(v.w - __bfloat162float(h3));
        ((__nv_bfloat162*)g_xl)[i * 2 + 0] = ll0;
        ((__nv_bfloat162*)g_xl)[i * 2 + 1] = ll1;
    }
}

// ============================ HMMA GEMM: C = relu(A @ W^T + bias) ============================
#define BK 32
#define NSTAGE (CDIM / BK)          // 16
#define RPITCH 80
#define T_TB (128 * RPITCH)         // 10240 per operand tile
#define STAGEB (4 * T_TB)           // 40960: [Ah, Al, Wh, Wl]
#define GEMM_SMEM (2 * STAGEB)      // 81920

__global__ __launch_bounds__(256, 2)
void gemm_tc(float* __restrict__ Cext, int mode)
{
    extern __shared__ char smem[];
    const __nv_bfloat16 *Ah, *Al, *Wh, *Wl;
    const float* bias;
    float* C;
    int bn;
    if (mode == 0) {
        int sel = blockIdx.x >> 2;          // 0=q, 1=k, 2=v
        bn = (blockIdx.x & 3) * 128;
        Ah = g_xh; Al = g_xl;
        Wh = (sel == 0) ? g_whq : (sel == 1) ? g_whk : g_whv;
        Wl = (sel == 0) ? g_wlq : (sel == 1) ? g_wlk : g_wlv;
        bias = (sel == 0) ? g_bq : (sel == 1) ? g_bk : g_bv;
        C = (sel == 0) ? g_q : (sel == 1) ? g_k : g_v;
    } else {
        bn = blockIdx.x * 128;
        Ah = g_atth; Al = g_attl;
        Wh = g_whp; Wl = g_wlp; bias = g_bp;
        C = Cext;
    }
    const int bm = blockIdx.y * 128;

    const uint32_t sb = smem_u32(smem);
    const int tid = threadIdx.x;
    const int wid = tid >> 5, lane = tid & 31;
    const int wm = wid & 1, wn = wid >> 1;   // 2(m) x 4(n)

    const __nv_bfloat16* srcA[2] = { Ah + (size_t)bm * CDIM, Al + (size_t)bm * CDIM };
    const __nv_bfloat16* srcW[2] = { Wh + (size_t)bn * CDIM, Wl + (size_t)bn * CDIM };

    auto load_stage = [&](int s, int buf) {
        uint32_t sbase = sb + buf * STAGEB;
        int kof = s * BK;
#pragma unroll
        for (int t = 0; t < 8; ++t) {
            int idx = tid + t * 256;
            int ten = idx >> 9;
            int v = idx & 511;
            int row = v >> 2, ch = v & 3;
            const __nv_bfloat16* g =
                (ten < 2 ? srcA[ten] : srcW[ten - 2]) + (size_t)row * CDIM + kof + ch * 8;
            cp16(sbase + ten * T_TB + row * RPITCH + ch * 16, g);
        }
        cp_commit();
    };

    float acc[4][4][4];
#pragma unroll
    for (int i = 0; i < 4; ++i)
#pragma unroll
        for (int j = 0; j < 4; ++j)
#pragma unroll
            for (int k = 0; k < 4; ++k) acc[i][j][k] = 0.f;

    const int g8 = lane >> 3, l8 = lane & 7;
    const int a_row = (g8 & 1) * 8 + l8;
    const int a_k = (g8 >> 1) * 8;
    const int w_row = (g8 >> 1) * 8 + l8;
    const int w_k = (g8 & 1) * 8;

    const uint32_t aoffL = (wm * 64 + a_row) * RPITCH + a_k * 2;
    const uint32_t woffL = (wn * 32 + w_row) * RPITCH + w_k * 2;

    load_stage(0, 0);

    for (int s = 0; s < NSTAGE; ++s) {
        cp_wait<0>();
        __syncthreads();
        if (s + 1 < NSTAGE) load_stage(s + 1, (s + 1) & 1);

        const uint32_t base = sb + (s & 1) * STAGEB;
        const uint32_t aB = base + aoffL;
        const uint32_t wB = base + 2 * T_TB + woffL;

#pragma unroll
        for (int kk = 0; kk < BK; kk += 16) {
            uint32_t whf[2][4], wlf[2][4];
#pragma unroll
            for (int j = 0; j < 2; ++j) {
                uint32_t off = wB + j * (16 * RPITCH) + kk * 2;
                ldsm4(whf[j], off);
                ldsm4(wlf[j], off + T_TB);
            }
            uint32_t ahf[2][4], alf[2][4];
            ldsm4(ahf[0], aB + kk * 2);
            ldsm4(alf[0], aB + kk * 2 + T_TB);
#pragma unroll
            for (int mi = 0; mi < 4; ++mi) {
                const int cur = mi & 1;
                if (mi < 3) {
                    uint32_t off = aB + (mi + 1) * (16 * RPITCH) + kk * 2;
                    ldsm4(ahf[cur ^ 1], off);
                    ldsm4(alf[cur ^ 1], off + T_TB);
                }
#pragma unroll
                for (int nj = 0; nj < 4; ++nj)
                    mma_bf16(acc[mi][nj], ahf[cur], whf[nj >> 1][(nj & 1) * 2], whf[nj >> 1][(nj & 1) * 2 + 1]);
#pragma unroll
                for (int nj = 0; nj < 4; ++nj)
                    mma_bf16(acc[mi][nj], ahf[cur], wlf[nj >> 1][(nj & 1) * 2], wlf[nj >> 1][(nj & 1) * 2 + 1]);
#pragma unroll
                for (int nj = 0; nj < 4; ++nj)
                    mma_bf16(acc[mi][nj], alf[cur], whf[nj >> 1][(nj & 1) * 2], whf[nj >> 1][(nj & 1) * 2 + 1]);
            }
        }
    }

    const int r_in = lane >> 2;
    const int c_in = (lane & 3) * 2;
#pragma unroll
    for (int mi = 0; mi < 4; ++mi) {
        int r0 = bm + wm * 64 + mi * 16 + r_in;
#pragma unroll
        for (int nj = 0; nj < 4; ++nj) {
            int c0 = bn + wn * 32 + nj * 8 + c_in;
            float b0 = bias[c0], b1 = bias[c0 + 1];
            float2 lo, hi;
            lo.x = fmaxf(acc[mi][nj][0] + b0, 0.f);
            lo.y = fmaxf(acc[mi][nj][1] + b1, 0.f);
            hi.x = fmaxf(acc[mi][nj][2] + b0, 0.f);
            hi.y = fmaxf(acc[mi][nj][3] + b1, 0.f);
            *(float2*)(C + (size_t)r0 * CDIM + c0) = lo;
            *(float2*)(C + (size_t)(r0 + 8) * CDIM + c0) = hi;
        }
    }
}

// ============================ attention middle ============================
// v2: grid (64 bh, 8 parts), 128 threads, 8(d)x4(e) per thread. Each part: 128 n-rows.
__global__ __launch_bounds__(128)
void kv_outer_partial()
{
    int bh = blockIdx.x, part = blockIdx.y;
    int b = bh >> 3, h = bh & 7;
    __shared__ float Ks[32][64];
    __shared__ float Vs[32][64];
    int tid = threadIdx.x;            // 128
    int tx = tid & 15;                // e-group: 4 per thread
    int ty = tid >> 4;                // d-group: 8 per thread (0..7)
    const float* kbase = g_k + ((size_t)b * 1024) * CDIM + h * 64;
    const float* vbase = g_v + ((size_t)b * 1024) * CDIM + h * 64;

    float acc[8][4];
#pragma unroll
    for (int i = 0; i < 8; ++i)
#pragma unroll
        for (int j = 0; j < 4; ++j) acc[i][j] = 0.f;

    int nbeg = part * 128;
    for (int n0 = nbeg; n0 < nbeg + 128; n0 += 32) {
#pragma unroll
        for (int u = 0; u < 4; ++u) {
            int v = tid + u * 128;
            int r = v >> 4, c4 = v & 15;
            *(float4*)&Ks[r][c4 * 4] = *(const float4*)(kbase + (size_t)(n0 + r) * CDIM + c4 * 4);
            *(float4*)&Vs[r][c4 * 4] = *(const float4*)(vbase + (size_t)(n0 + r) * CDIM + c4 * 4);
        }
        __syncthreads();
#pragma unroll
        for (int nn = 0; nn < 32; ++nn) {
            float4 k0 = *(const float4*)&Ks[nn][ty * 8];
            float4 k1 = *(const float4*)&Ks[nn][ty * 8 + 4];
            float4 vv = *(const float4*)&Vs[nn][tx * 4];
            float ka[8] = {k0.x, k0.y, k0.z, k0.w, k1.x, k1.y, k1.z, k1.w};
            float va[4] = {vv.x, vv.y, vv.z, vv.w};
#pragma unroll
            for (int i = 0; i < 8; ++i)
#pragma unroll
                for (int j = 0; j < 4; ++j)
                    acc[i][j] = fmaf(ka[i], va[j], acc[i][j]);
        }
        __syncthreads();
    }

    float* mp = g_mpart + ((size_t)part * 64 + bh) * 4096;
#pragma unroll
    for (int i = 0; i < 8; ++i) {
        float* row = mp + (ty * 8 + i) * 64 + tx * 4;
        float4 o = {acc[i][0], acc[i][1], acc[i][2], acc[i][3]};
        *(float4*)row = o;
    }
}

// reduce 8 partials -> g_m (with SCALE)
__global__ void kv_reduce8()
{
    int i = blockIdx.x * blockDim.x + threadIdx.x;   // over 65536 float4
    float4 s = ((const float4*)g_mpart)[i];
#pragma unroll
    for (int p = 1; p < 8; ++p) {
        float4 t = ((const float4*)g_mpart)[p * 65536 + i];
        s.x += t.x; s.y += t.y; s.z += t.z; s.w += t.w;
    }
    s.x *= SCALE_ATTN; s.y *= SCALE_ATTN; s.z *= SCALE_ATTN; s.w *= SCALE_ATTN;
    ((float4*)g_m)[i] = s;
}

// att = relu(q @ M) -> bf16 hi/lo
__global__ __launch_bounds__(256)
void qm_relu_split()
{
    int nt = blockIdx.x, h = blockIdx.y, b = blockIdx.z;
    __shared__ float Qs[64][65];
    __shared__ float Ms[64][68];
    int tid = threadIdx.x;
    const float* qbase = g_q + ((size_t)(b * 1024 + nt * 64)) * CDIM + h * 64;
    const float* mbase = g_m + (size_t)(b * 8 + h) * 4096;
#pragma unroll
    for (int u = 0; u < 4; ++u) {
        int v = tid + u * 256;
        int r = v >> 4, c4 = v & 15;
        float4 t = *(const float4*)(qbase + (size_t)r * CDIM + c4 * 4);
        Qs[r][c4 * 4 + 0] = t.x; Qs[r][c4 * 4 + 1] = t.y;
        Qs[r][c4 * 4 + 2] = t.z; Qs[r][c4 * 4 + 3] = t.w;
        *(float4*)&Ms[r][c4 * 4] = *(const float4*)(mbase + r * 64 + c4 * 4);
    }
    __syncthreads();
    int r = tid >> 2, quarter = tid & 3;
    float acc[16];
#pragma unroll
    for (int e = 0; e < 16; ++e) acc[e] = 0.f;
#pragma unroll
    for (int d = 0; d < 64; ++d) {
        float qv = Qs[r][d];
#pragma unroll
        for (int e4 = 0; e4 < 4; ++e4) {
            float4 m = *(const float4*)&Ms[d][quarter * 16 + e4 * 4];
            acc[e4 * 4 + 0] = fmaf(qv, m.x, acc[e4 * 4 + 0]);
            acc[e4 * 4 + 1] = fmaf(qv, m.y, acc[e4 * 4 + 1]);
            acc[e4 * 4 + 2] = fmaf(qv, m.z, acc[e4 * 4 + 2]);
            acc[e4 * 4 + 3] = fmaf(qv, m.w, acc[e4 * 4 + 3]);
        }
    }
    size_t obase = ((size_t)(b * 1024 + nt * 64 + r)) * CDIM + h * 64 + quarter * 16;
#pragma unroll
    for (int e2 = 0; e2 < 8; ++e2) {
        float v0 = fmaxf(acc[e2 * 2 + 0], 0.f);
        float v1 = fmaxf(acc[e2 * 2 + 1], 0.f);
        __nv_bfloat16 h0 = __float2bfloat16(v0);
        __nv_bfloat16 h1 = __float2bfloat16(v1);
        __nv_bfloat162 hh; hh.x = h0; hh.y = h1;
        __nv_bfloat162 ll;
        ll.x = __float2bfloat16(v0 - __bfloat162float(h0));
        ll.y = __float2bfloat16(v1 - __bfloat162float(h1));
        *(__nv_bfloat162*)(g_atth + obase + e2 * 2) = hh;
        *(__nv_bfloat162*)(g_attl + obase + e2 * 2) = ll;
    }
}

// ============================ host launch ============================
extern "C" void kernel_launch(void* const* d_in, const int* in_sizes, int n_in,
                              void* d_out, int out_size)
{
    (void)in_sizes; (void)n_in; (void)out_size;
    const float* x = (const float*)d_in[0];
    const float** p = (const float**)(d_in + 1);   // 24 params: 4 sets x 6

    cudaFuncSetAttribute(gemm_tc, cudaFuncAttributeMaxDynamicSharedMemorySize, GEMM_SMEM);

    prep_all<<<8192, 256>>>(x,
        p[0], p[1], p[2], p[3], p[4], p[5],
        p[6], p[7], p[8], p[9], p[10], p[11],
        p[12], p[13], p[14], p[15], p[16], p[17],
        p[18], p[19], p[20], p[21], p[22], p[23]);

    // fused QKV: grid (12, 64) = 768 CTAs, 2 CTAs/SM
    gemm_tc<<<dim3(12, 64), 256, GEMM_SMEM>>>(nullptr, 0);

    kv_outer_partial<<<dim3(64, 8), 128>>>();
    kv_reduce8<<<256, 256>>>();
    qm_relu_split<<<dim3(16, 8, 8), 256>>>();

    // P projection
    gemm_tc<<<dim3(4, 64), 256, GEMM_SMEM>>>((float*)d_out, 1);
}